// round 7
// baseline (speedup 1.0000x reference)
#include <cuda_runtime.h>
#include <cstdint>
#include <math.h>

#define BB 2
#define LL 2048
#define DD 1024
#define HH 16
#define HD 64
#define MM (BB*LL)        // 4096
#define N_QKV (3*DD)      // 3072

// Scratch (allocation-free rule: __device__ globals)
__device__ float g_q[BB*HH*LL*HD];   // (b,h,l,d)  tf32-rounded, q pre-scaled by 1/8
__device__ float g_k[BB*HH*LL*HD];
__device__ float g_v[BB*HH*LL*HD];
__device__ float g_o[MM*DD];         // (b,l,h*64+d) tf32-rounded attention output
__device__ float g_gate[BB*LL];
__device__ float g_xt[MM*DD];        // tf32-rounded x
__device__ float g_wq[N_QKV*DD];     // tf32-rounded qkv_w
__device__ float g_wo[DD*DD];        // tf32-rounded out_w

// ---------------------------------------------------------------------------
// helpers
// ---------------------------------------------------------------------------
__device__ __forceinline__ unsigned f2tf32(float f) {
    unsigned u;
    asm("cvt.rna.tf32.f32 %0, %1;" : "=r"(u) : "f"(f));
    return u;
}

__device__ __forceinline__ void mma_tf32(float c[4], const unsigned a[4], const unsigned b[2]) {
    asm("mma.sync.aligned.m16n8k8.row.col.f32.tf32.tf32.f32 "
        "{%0,%1,%2,%3}, {%4,%5,%6,%7}, {%8,%9}, {%0,%1,%2,%3};"
        : "+f"(c[0]), "+f"(c[1]), "+f"(c[2]), "+f"(c[3])
        : "r"(a[0]), "r"(a[1]), "r"(a[2]), "r"(a[3]), "r"(b[0]), "r"(b[1]));
}

// ---------------------------------------------------------------------------
// mma.sync GEMM, 64x64 warp tiles. Block 128x128, 128 threads / 4 warps.
// C[m][n] = sum_k A[m][k]*W[n][k]. Smem rows padded to 20 floats
// (conflict-free: lr4*20 mod 32 hits 8 distinct banks x 4 consecutive).
// LDS-per-HMMA = 1.0 reg32 (vs 1.5 in the 64x32 layout) -> attacks the
// measured LSU bottleneck (tensor=35%, L1=64% in R2).
// ---------------------------------------------------------------------------
struct GemmFrag {
    float acc[4][8][4];
};

__device__ __forceinline__ void gemm128_main(
    const float* __restrict__ A, const float* __restrict__ W,
    int bm, int bn, float* As, float* Bs, GemmFrag& fr)
{
    const int tid = threadIdx.x, lane = tid & 31, wid = tid >> 5;
    const int wm = (wid & 1) << 6, wn = (wid >> 1) << 6;
    const int lr4 = lane >> 2, lc = lane & 3;

#pragma unroll
    for (int mt = 0; mt < 4; mt++)
#pragma unroll
        for (int nt = 0; nt < 8; nt++)
#pragma unroll
            for (int i = 0; i < 4; i++) fr.acc[mt][nt][i] = 0.f;

    const float* Ag = A + (size_t)(bm + tid) * DD;
    const float* Bg = W + (size_t)(bn + tid) * DD;

    for (int k0 = 0; k0 < DD; k0 += 16) {
        float4 av[4], bv[4];
#pragma unroll
        for (int i = 0; i < 4; i++) {
            av[i] = *(const float4*)(Ag + k0 + i * 4);
            bv[i] = *(const float4*)(Bg + k0 + i * 4);
        }
        __syncthreads();
#pragma unroll
        for (int i = 0; i < 4; i++) {
            *(float4*)&As[tid * 20 + i * 4] = av[i];
            *(float4*)&Bs[tid * 20 + i * 4] = bv[i];
        }
        __syncthreads();
        const unsigned* Au = (const unsigned*)As;
        const unsigned* Bu = (const unsigned*)Bs;
#pragma unroll
        for (int ks = 0; ks < 16; ks += 8) {
            unsigned a[4][4], b[8][2];
#pragma unroll
            for (int mt = 0; mt < 4; mt++) {
                int base = (wm + mt * 16 + lr4) * 20 + ks + lc;
                a[mt][0] = Au[base];       a[mt][1] = Au[base + 160];
                a[mt][2] = Au[base + 4];   a[mt][3] = Au[base + 164];
            }
#pragma unroll
            for (int nt = 0; nt < 8; nt++) {
                int bb = (wn + nt * 8 + lr4) * 20 + ks + lc;
                b[nt][0] = Bu[bb]; b[nt][1] = Bu[bb + 4];
            }
#pragma unroll
            for (int mt = 0; mt < 4; mt++)
#pragma unroll
                for (int nt = 0; nt < 8; nt++) mma_tf32(fr.acc[mt][nt], a[mt], b[nt]);
        }
    }
}

// ---------------------------------------------------------------------------
// QKV GEMM: M=4096, N=3072, K=1024. Grid (24, 32).
// Epilogue scatters tf32-rounded q(*0.125)/k/v into (b,h,l,d).
// ---------------------------------------------------------------------------
__device__ __forceinline__ void qkv_store(int m, int n, float v0, float v1) {
    int b = m >> 11, l = m & 2047;
    int which = n >> 10, h = (n >> 6) & 15, d = n & 63;
    float* dst = (which == 0) ? g_q : ((which == 1) ? g_k : g_v);
    if (which == 0) { v0 *= 0.125f; v1 *= 0.125f; }
    float2 val;
    val.x = __uint_as_float(f2tf32(v0));
    val.y = __uint_as_float(f2tf32(v1));
    *(float2*)(dst + ((size_t)((b << 4) + h) * LL + l) * HD + d) = val;
}

__global__ __launch_bounds__(128, 2) void qkv_gemm128() {
    __shared__ float As[128 * 20];
    __shared__ float Bs[128 * 20];
    const int bm = blockIdx.y << 7, bn = blockIdx.x << 7;
    const int lane = threadIdx.x & 31, wid = threadIdx.x >> 5;
    const int wm = (wid & 1) << 6, wn = (wid >> 1) << 6;
    const int lr4 = lane >> 2, lc = lane & 3;

    GemmFrag fr;
    gemm128_main(g_xt, g_wq, bm, bn, As, Bs, fr);

#pragma unroll
    for (int mt = 0; mt < 4; mt++)
#pragma unroll
        for (int nt = 0; nt < 8; nt++) {
            int m = bm + wm + mt * 16 + lr4;
            int n = bn + wn + (nt << 3) + (lc << 1);
            qkv_store(m,     n, fr.acc[mt][nt][0], fr.acc[mt][nt][1]);
            qkv_store(m + 8, n, fr.acc[mt][nt][2], fr.acc[mt][nt][3]);
        }
}

// ---------------------------------------------------------------------------
// Out GEMM: M=4096, N=1024, K=1024. Grid (8, 32). + bias
// ---------------------------------------------------------------------------
__global__ __launch_bounds__(128, 2) void out_gemm128(
    const float* __restrict__ bias, float* __restrict__ C)
{
    __shared__ float As[128 * 20];
    __shared__ float Bs[128 * 20];
    const int bm = blockIdx.y << 7, bn = blockIdx.x << 7;
    const int lane = threadIdx.x & 31, wid = threadIdx.x >> 5;
    const int wm = (wid & 1) << 6, wn = (wid >> 1) << 6;
    const int lr4 = lane >> 2, lc = lane & 3;

    GemmFrag fr;
    gemm128_main(g_o, g_wo, bm, bn, As, Bs, fr);

#pragma unroll
    for (int mt = 0; mt < 4; mt++)
#pragma unroll
        for (int nt = 0; nt < 8; nt++) {
            int m = bm + wm + mt * 16 + lr4;
            int n = bn + wn + (nt << 3) + (lc << 1);
            float2 r0v, r1v;
            r0v.x = fr.acc[mt][nt][0] + bias[n];
            r0v.y = fr.acc[mt][nt][1] + bias[n + 1];
            r1v.x = fr.acc[mt][nt][2] + bias[n];
            r1v.y = fr.acc[mt][nt][3] + bias[n + 1];
            *(float2*)&C[(size_t)m * DD + n]       = r0v;
            *(float2*)&C[(size_t)(m + 8) * DD + n] = r1v;
        }
}

// ---------------------------------------------------------------------------
// elementwise tf32 rounding (one pass per operand; paid once, not per reuse)
// ---------------------------------------------------------------------------
__global__ void cvt_tf32_kernel(const float* __restrict__ src, float* __restrict__ dst, int n) {
    int i = blockIdx.x * blockDim.x + threadIdx.x;
    if (i < n) dst[i] = __uint_as_float(f2tf32(src[i]));
}

// ---------------------------------------------------------------------------
// Gate: softmax over L of sqrt(Gr^2+Gi^2+eps)/temp, * gate_scale
// ---------------------------------------------------------------------------
__global__ __launch_bounds__(256) void gate_kernel(
    const float* __restrict__ G, const float* __restrict__ gs_p,
    const float* __restrict__ lt_p)
{
    __shared__ float sm[256];
    const int b = blockIdx.x, tid = threadIdx.x;
    const float inv_temp = __expf(-lt_p[0]);

    float z[8];
    float mx = -INFINITY;
#pragma unroll
    for (int i = 0; i < 8; i++) {
        int l = i * 256 + tid;
        float gr = G[(b * LL + l) * 2 + 0];
        float gi = G[(b * LL + l) * 2 + 1];
        z[i] = sqrtf(gr * gr + gi * gi + 1e-7f) * inv_temp;
        mx = fmaxf(mx, z[i]);
    }
    sm[tid] = mx; __syncthreads();
    for (int s = 128; s > 0; s >>= 1) {
        if (tid < s) sm[tid] = fmaxf(sm[tid], sm[tid + s]);
        __syncthreads();
    }
    const float gmax = sm[0];
    __syncthreads();

    float e[8]; float lsum = 0.f;
#pragma unroll
    for (int i = 0; i < 8; i++) { e[i] = __expf(z[i] - gmax); lsum += e[i]; }
    sm[tid] = lsum; __syncthreads();
    for (int s = 128; s > 0; s >>= 1) {
        if (tid < s) sm[tid] += sm[tid + s];
        __syncthreads();
    }
    const float inv_sum = 1.f / sm[0];
    const float gs = gs_p[0];
#pragma unroll
    for (int i = 0; i < 8; i++)
        g_gate[b * LL + i * 256 + tid] = e[i] * inv_sum * gs;
}

// ---------------------------------------------------------------------------
// Flash attention (mma.sync tf32) — unchanged (known good, 300us in R2).
// ---------------------------------------------------------------------------
__global__ __launch_bounds__(256, 2) void attn_tc() {
    __shared__ float Ks[32 * 68];
    __shared__ float Vs[64 * 36];
    __shared__ float Ps[128 * 36];

    const int tid = threadIdx.x, lane = tid & 31, wid = tid >> 5;
    const int bh = blockIdx.y, qbase = blockIdx.x << 7;
    const int lr4 = lane >> 2, lc = lane & 3;
    const int rq = wid * 16 + lr4;

    const float* Qg = g_q + ((size_t)bh * LL + qbase) * HD;
    const float* Kg = g_k + (size_t)bh * LL * HD;
    const float* Vg = g_v + (size_t)bh * LL * HD;

    unsigned qf[8][4];
#pragma unroll
    for (int k = 0; k < 8; k++) {
        int c = k * 8 + lc;
        qf[k][0] = __float_as_uint(Qg[rq * 64 + c]);
        qf[k][1] = __float_as_uint(Qg[(rq + 8) * 64 + c]);
        qf[k][2] = __float_as_uint(Qg[rq * 64 + c + 4]);
        qf[k][3] = __float_as_uint(Qg[(rq + 8) * 64 + c + 4]);
    }

    float oacc[8][4];
#pragma unroll
    for (int nt = 0; nt < 8; nt++)
#pragma unroll
        for (int i = 0; i < 4; i++) oacc[nt][i] = 0.f;
    float m_i[2] = {-INFINITY, -INFINITY};
    float l_i[2] = {0.f, 0.f};

    const int lkey = tid >> 4, lkd = (tid & 15) << 2;
    const int vkey = tid & 31, vd0 = (tid >> 5) << 2;

    for (int kt = 0; kt < LL / 32; kt++) {
        const int kb = kt << 5;
        __syncthreads();
#pragma unroll
        for (int p = 0; p < 2; p++) {
            float4 kv = *(const float4*)(Kg + (size_t)(kb + lkey + p * 16) * 64 + lkd);
            *(float4*)&Ks[(lkey + p * 16) * 68 + lkd] = kv;
        }
#pragma unroll
        for (int p = 0; p < 2; p++) {
            int d0 = vd0 + p * 32;
            float4 vv = *(const float4*)(Vg + (size_t)(kb + vkey) * 64 + d0);
            Vs[(d0 + 0) * 36 + vkey] = vv.x; Vs[(d0 + 1) * 36 + vkey] = vv.y;
            Vs[(d0 + 2) * 36 + vkey] = vv.z; Vs[(d0 + 3) * 36 + vkey] = vv.w;
        }
        __syncthreads();

        float sacc[4][4];
#pragma unroll
        for (int nt = 0; nt < 4; nt++)
#pragma unroll
            for (int i = 0; i < 4; i++) sacc[nt][i] = 0.f;
        const unsigned* Ku = (const unsigned*)Ks;
#pragma unroll
        for (int k = 0; k < 8; k++) {
            unsigned b[4][2];
#pragma unroll
            for (int nt = 0; nt < 4; nt++) {
                int bb = (nt * 8 + lr4) * 68 + k * 8 + lc;
                b[nt][0] = Ku[bb]; b[nt][1] = Ku[bb + 4];
            }
#pragma unroll
            for (int nt = 0; nt < 4; nt++) mma_tf32(sacc[nt], qf[k], b[nt]);
        }

#pragma unroll
        for (int h2 = 0; h2 < 2; h2++) {
            float rm = -INFINITY;
#pragma unroll
            for (int nt = 0; nt < 4; nt++)
                rm = fmaxf(rm, fmaxf(sacc[nt][h2 * 2], sacc[nt][h2 * 2 + 1]));
            rm = fmaxf(rm, __shfl_xor_sync(0xffffffffu, rm, 1));
            rm = fmaxf(rm, __shfl_xor_sync(0xffffffffu, rm, 2));
            float mn = fmaxf(m_i[h2], rm);
            float corr = __expf(m_i[h2] - mn);
            m_i[h2] = mn;
            float rs = 0.f;
#pragma unroll
            for (int nt = 0; nt < 4; nt++) {
                float p0 = __expf(sacc[nt][h2 * 2] - mn);
                float p1 = __expf(sacc[nt][h2 * 2 + 1] - mn);
                rs += p0 + p1;
                float2 pv;
                pv.x = __uint_as_float(f2tf32(p0));
                pv.y = __uint_as_float(f2tf32(p1));
                *(float2*)&Ps[(rq + h2 * 8) * 36 + nt * 8 + lc * 2] = pv;
            }
            rs += __shfl_xor_sync(0xffffffffu, rs, 1);
            rs += __shfl_xor_sync(0xffffffffu, rs, 2);
            l_i[h2] = l_i[h2] * corr + rs;
#pragma unroll
            for (int nt = 0; nt < 8; nt++) {
                oacc[nt][h2 * 2]     *= corr;
                oacc[nt][h2 * 2 + 1] *= corr;
            }
        }
        __syncwarp();

        const unsigned* Pu = (const unsigned*)Ps;
        const unsigned* Vu = (const unsigned*)Vs;
#pragma unroll
        for (int k = 0; k < 4; k++) {
            unsigned a[4];
            int ab = rq * 36 + k * 8 + lc;
            a[0] = Pu[ab];           a[1] = Pu[ab + 8 * 36];
            a[2] = Pu[ab + 4];       a[3] = Pu[ab + 8 * 36 + 4];
#pragma unroll
            for (int nt = 0; nt < 8; nt++) {
                unsigned b[2];
                int bb = (nt * 8 + lr4) * 36 + k * 8 + lc;
                b[0] = Vu[bb]; b[1] = Vu[bb + 4];
                mma_tf32(oacc[nt], a, b);
            }
        }
    }

    const int b = bh >> 4, h = bh & 15;
#pragma unroll
    for (int h2 = 0; h2 < 2; h2++) {
        int q = qbase + rq + h2 * 8;
        float sc = g_gate[b * LL + q] / l_i[h2];
        float* dst = g_o + ((size_t)(b * LL + q)) * DD + h * HD;
#pragma unroll
        for (int nt = 0; nt < 8; nt++) {
            int d = nt * 8 + lc * 2;
            float2 ov;
            ov.x = __uint_as_float(f2tf32(oacc[nt][h2 * 2] * sc));
            ov.y = __uint_as_float(f2tf32(oacc[nt][h2 * 2 + 1] * sc));
            *(float2*)(dst + d) = ov;
        }
    }
}

// ---------------------------------------------------------------------------
extern "C" void kernel_launch(void* const* d_in, const int* in_sizes, int n_in,
                              void* d_out, int out_size)
{
    const float* x    = (const float*)d_in[0];
    const float* G    = (const float*)d_in[1];
    const float* qkvw = (const float*)d_in[2];
    const float* outw = (const float*)d_in[3];
    const float* outb = (const float*)d_in[4];
    const float* gsc  = (const float*)d_in[5];
    const float* ltm  = (const float*)d_in[6];
    float* out = (float*)d_out;

    float* xt; cudaGetSymbolAddress((void**)&xt, g_xt);
    float* wq; cudaGetSymbolAddress((void**)&wq, g_wq);
    float* wo; cudaGetSymbolAddress((void**)&wo, g_wo);

    cvt_tf32_kernel<<<(MM * DD) / 256, 256>>>(x, xt, MM * DD);
    cvt_tf32_kernel<<<(N_QKV * DD) / 256, 256>>>(qkvw, wq, N_QKV * DD);
    cvt_tf32_kernel<<<(DD * DD) / 256, 256>>>(outw, wo, DD * DD);

    dim3 g1(N_QKV / 128, MM / 128);   // (24, 32)
    qkv_gemm128<<<g1, 128>>>();

    gate_kernel<<<BB, 256>>>(G, gsc, ltm);

    dim3 g2(LL / 128, BB * HH);       // (16, 32)
    attn_tc<<<g2, 256>>>();

    dim3 g3(DD / 128, MM / 128);      // (8, 32)
    out_gemm128<<<g3, 128>>>(outb, out);
}

// round 8
// speedup vs baseline: 1.2323x; 1.2323x over previous
#include <cuda_runtime.h>
#include <cstdint>
#include <math.h>

#define BB 2
#define LL 2048
#define DD 1024
#define HH 16
#define HD 64
#define MM (BB*LL)        // 4096
#define N_QKV (3*DD)      // 3072

// Scratch (allocation-free rule: __device__ globals)
__device__ float g_q[BB*HH*LL*HD];   // (b,h,l,d)  tf32-rounded, q pre-scaled by 1/8
__device__ float g_k[BB*HH*LL*HD];
__device__ float g_v[BB*HH*LL*HD];
__device__ float g_o[MM*DD];         // (b,l,h*64+d) tf32-rounded attention output
__device__ float g_gate[BB*LL];
__device__ float g_xt[MM*DD];        // tf32-rounded x
__device__ float g_wq[N_QKV*DD];     // tf32-rounded qkv_w
__device__ float g_wo[DD*DD];        // tf32-rounded out_w

// ---------------------------------------------------------------------------
// helpers
// ---------------------------------------------------------------------------
__device__ __forceinline__ unsigned f2tf32(float f) {
    unsigned u;
    asm("cvt.rna.tf32.f32 %0, %1;" : "=r"(u) : "f"(f));
    return u;
}

__device__ __forceinline__ void mma_tf32(float c[4], const unsigned a[4], const unsigned b[2]) {
    asm("mma.sync.aligned.m16n8k8.row.col.f32.tf32.tf32.f32 "
        "{%0,%1,%2,%3}, {%4,%5,%6,%7}, {%8,%9}, {%0,%1,%2,%3};"
        : "+f"(c[0]), "+f"(c[1]), "+f"(c[2]), "+f"(c[3])
        : "r"(a[0]), "r"(a[1]), "r"(a[2]), "r"(a[3]), "r"(b[0]), "r"(b[1]));
}

__device__ __forceinline__ uint32_t smem_u32(const void* p) {
    uint32_t a;
    asm("{ .reg .u64 t; cvta.to.shared.u64 t, %1; cvt.u32.u64 %0, t; }" : "=r"(a) : "l"(p));
    return a;
}

__device__ __forceinline__ void cp_async16(uint32_t dst, const void* src) {
    asm volatile("cp.async.cg.shared.global [%0], [%1], 16;" :: "r"(dst), "l"(src) : "memory");
}
#define CP_COMMIT() asm volatile("cp.async.commit_group;" ::: "memory")
#define CP_WAIT(n)  asm volatile("cp.async.wait_group %0;" :: "n"(n) : "memory")

// ---------------------------------------------------------------------------
// GEMM mainloop: R2 geometry (proven: 126 regs, occ 22.8%) + cp.async
// 2-stage double buffering. Block 128x128, 256 threads / 8 warps, 64x32
// warp tiles, K-slab 16. Smem rows padded to 20 floats (conflict-free).
// ---------------------------------------------------------------------------
#define BUF_FLOATS (128 * 20)

__device__ __forceinline__ void gemm_cp_main(
    const float* __restrict__ A, const float* __restrict__ W,
    int bm, int bn, float* As, float* Bs, float acc[4][4][4])
{
    const int tid = threadIdx.x, lane = tid & 31, wid = tid >> 5;
    const int wm = (wid & 1) << 6, wn = (wid >> 1) << 5;
    const int lr4 = lane >> 2, lc = lane & 3;

#pragma unroll
    for (int mt = 0; mt < 4; mt++)
#pragma unroll
        for (int nt = 0; nt < 4; nt++)
#pragma unroll
            for (int i = 0; i < 4; i++) acc[mt][nt][i] = 0.f;

    const int row = tid >> 2, kk = (tid & 3) << 2;
    const float* Ag0 = A + (size_t)(bm + row) * DD + kk;
    const float* Ag1 = Ag0 + (size_t)64 * DD;
    const float* Bg0 = W + (size_t)(bn + row) * DD + kk;
    const float* Bg1 = Bg0 + (size_t)64 * DD;
    const uint32_t sA = smem_u32(As), sB = smem_u32(Bs);
    const uint32_t dA0 = sA + (row * 20 + kk) * 4;
    const uint32_t dA1 = sA + ((row + 64) * 20 + kk) * 4;
    const uint32_t dB0 = sB + (row * 20 + kk) * 4;
    const uint32_t dB1 = sB + ((row + 64) * 20 + kk) * 4;

    // prologue: slab 0 -> buf 0
    cp_async16(dA0, Ag0); cp_async16(dA1, Ag1);
    cp_async16(dB0, Bg0); cp_async16(dB1, Bg1);
    CP_COMMIT();

    for (int slab = 0; slab < 64; slab++) {
        const int buf = slab & 1;
        if (slab < 63) {
            const uint32_t off = (uint32_t)(buf ^ 1) * (BUF_FLOATS * 4);
            const int g = (slab + 1) * 16;
            cp_async16(dA0 + off, Ag0 + g); cp_async16(dA1 + off, Ag1 + g);
            cp_async16(dB0 + off, Bg0 + g); cp_async16(dB1 + off, Bg1 + g);
            CP_COMMIT();
            CP_WAIT(1);      // slab's own group complete
        } else {
            CP_WAIT(0);
        }
        __syncthreads();

        const unsigned* Au = (const unsigned*)(As + buf * BUF_FLOATS);
        const unsigned* Bu = (const unsigned*)(Bs + buf * BUF_FLOATS);
#pragma unroll
        for (int ks = 0; ks < 16; ks += 8) {
            unsigned a[4][4], b[4][2];
#pragma unroll
            for (int mt = 0; mt < 4; mt++) {
                int base = (wm + mt * 16 + lr4) * 20 + ks + lc;
                a[mt][0] = Au[base];       a[mt][1] = Au[base + 160];
                a[mt][2] = Au[base + 4];   a[mt][3] = Au[base + 164];
            }
#pragma unroll
            for (int nt = 0; nt < 4; nt++) {
                int bb = (wn + nt * 8 + lr4) * 20 + ks + lc;
                b[nt][0] = Bu[bb]; b[nt][1] = Bu[bb + 4];
            }
#pragma unroll
            for (int mt = 0; mt < 4; mt++)
#pragma unroll
                for (int nt = 0; nt < 4; nt++) mma_tf32(acc[mt][nt], a[mt], b[nt]);
        }
        __syncthreads();   // all warps done with buf before it is refilled
    }
}

// ---------------------------------------------------------------------------
// QKV GEMM: M=4096, N=3072, K=1024. Grid (24, 32).
// Epilogue scatters tf32-rounded q(*0.125)/k/v into (b,h,l,d).
// ---------------------------------------------------------------------------
__device__ __forceinline__ void qkv_store(int m, int n, float v0, float v1) {
    int b = m >> 11, l = m & 2047;
    int which = n >> 10, h = (n >> 6) & 15, d = n & 63;
    float* dst = (which == 0) ? g_q : ((which == 1) ? g_k : g_v);
    if (which == 0) { v0 *= 0.125f; v1 *= 0.125f; }
    float2 val;
    val.x = __uint_as_float(f2tf32(v0));
    val.y = __uint_as_float(f2tf32(v1));
    *(float2*)(dst + ((size_t)((b << 4) + h) * LL + l) * HD + d) = val;
}

__global__ __launch_bounds__(256, 2) void qkv_gemm_cp() {
    __shared__ float As[2 * BUF_FLOATS];
    __shared__ float Bs[2 * BUF_FLOATS];
    const int bm = blockIdx.y << 7, bn = blockIdx.x << 7;
    const int lane = threadIdx.x & 31, wid = threadIdx.x >> 5;
    const int wm = (wid & 1) << 6, wn = (wid >> 1) << 5;
    const int lr4 = lane >> 2, lc = lane & 3;

    float acc[4][4][4];
    gemm_cp_main(g_xt, g_wq, bm, bn, As, Bs, acc);

#pragma unroll
    for (int mt = 0; mt < 4; mt++)
#pragma unroll
        for (int nt = 0; nt < 4; nt++) {
            int m = bm + wm + mt * 16 + lr4;
            int n = bn + wn + (nt << 3) + (lc << 1);
            qkv_store(m,     n, acc[mt][nt][0], acc[mt][nt][1]);
            qkv_store(m + 8, n, acc[mt][nt][2], acc[mt][nt][3]);
        }
}

// ---------------------------------------------------------------------------
// Out GEMM: M=4096, N=1024, K=1024. Grid (8, 32). + bias
// ---------------------------------------------------------------------------
__global__ __launch_bounds__(256, 2) void out_gemm_cp(
    const float* __restrict__ bias, float* __restrict__ C)
{
    __shared__ float As[2 * BUF_FLOATS];
    __shared__ float Bs[2 * BUF_FLOATS];
    const int bm = blockIdx.y << 7, bn = blockIdx.x << 7;
    const int lane = threadIdx.x & 31, wid = threadIdx.x >> 5;
    const int wm = (wid & 1) << 6, wn = (wid >> 1) << 5;
    const int lr4 = lane >> 2, lc = lane & 3;

    float acc[4][4][4];
    gemm_cp_main(g_o, g_wo, bm, bn, As, Bs, acc);

#pragma unroll
    for (int mt = 0; mt < 4; mt++)
#pragma unroll
        for (int nt = 0; nt < 4; nt++) {
            int m = bm + wm + mt * 16 + lr4;
            int n = bn + wn + (nt << 3) + (lc << 1);
            float2 r0v, r1v;
            r0v.x = acc[mt][nt][0] + bias[n];
            r0v.y = acc[mt][nt][1] + bias[n + 1];
            r1v.x = acc[mt][nt][2] + bias[n];
            r1v.y = acc[mt][nt][3] + bias[n + 1];
            *(float2*)&C[(size_t)m * DD + n]       = r0v;
            *(float2*)&C[(size_t)(m + 8) * DD + n] = r1v;
        }
}

// ---------------------------------------------------------------------------
// elementwise tf32 rounding (one pass per operand; paid once, not per reuse)
// ---------------------------------------------------------------------------
__global__ void cvt_tf32_kernel(const float* __restrict__ src, float* __restrict__ dst, int n) {
    int i = blockIdx.x * blockDim.x + threadIdx.x;
    if (i < n) dst[i] = __uint_as_float(f2tf32(src[i]));
}

// ---------------------------------------------------------------------------
// Gate: softmax over L of sqrt(Gr^2+Gi^2+eps)/temp, * gate_scale
// ---------------------------------------------------------------------------
__global__ __launch_bounds__(256) void gate_kernel(
    const float* __restrict__ G, const float* __restrict__ gs_p,
    const float* __restrict__ lt_p)
{
    __shared__ float sm[256];
    const int b = blockIdx.x, tid = threadIdx.x;
    const float inv_temp = __expf(-lt_p[0]);

    float z[8];
    float mx = -INFINITY;
#pragma unroll
    for (int i = 0; i < 8; i++) {
        int l = i * 256 + tid;
        float gr = G[(b * LL + l) * 2 + 0];
        float gi = G[(b * LL + l) * 2 + 1];
        z[i] = sqrtf(gr * gr + gi * gi + 1e-7f) * inv_temp;
        mx = fmaxf(mx, z[i]);
    }
    sm[tid] = mx; __syncthreads();
    for (int s = 128; s > 0; s >>= 1) {
        if (tid < s) sm[tid] = fmaxf(sm[tid], sm[tid + s]);
        __syncthreads();
    }
    const float gmax = sm[0];
    __syncthreads();

    float e[8]; float lsum = 0.f;
#pragma unroll
    for (int i = 0; i < 8; i++) { e[i] = __expf(z[i] - gmax); lsum += e[i]; }
    sm[tid] = lsum; __syncthreads();
    for (int s = 128; s > 0; s >>= 1) {
        if (tid < s) sm[tid] += sm[tid + s];
        __syncthreads();
    }
    const float inv_sum = 1.f / sm[0];
    const float gs = gs_p[0];
#pragma unroll
    for (int i = 0; i < 8; i++)
        g_gate[b * LL + i * 256 + tid] = e[i] * inv_sum * gs;
}

// ---------------------------------------------------------------------------
// Flash attention (mma.sync tf32) — unchanged (known good, ~300us).
// ---------------------------------------------------------------------------
__global__ __launch_bounds__(256, 2) void attn_tc() {
    __shared__ float Ks[32 * 68];
    __shared__ float Vs[64 * 36];
    __shared__ float Ps[128 * 36];

    const int tid = threadIdx.x, lane = tid & 31, wid = tid >> 5;
    const int bh = blockIdx.y, qbase = blockIdx.x << 7;
    const int lr4 = lane >> 2, lc = lane & 3;
    const int rq = wid * 16 + lr4;

    const float* Qg = g_q + ((size_t)bh * LL + qbase) * HD;
    const float* Kg = g_k + (size_t)bh * LL * HD;
    const float* Vg = g_v + (size_t)bh * LL * HD;

    unsigned qf[8][4];
#pragma unroll
    for (int k = 0; k < 8; k++) {
        int c = k * 8 + lc;
        qf[k][0] = __float_as_uint(Qg[rq * 64 + c]);
        qf[k][1] = __float_as_uint(Qg[(rq + 8) * 64 + c]);
        qf[k][2] = __float_as_uint(Qg[rq * 64 + c + 4]);
        qf[k][3] = __float_as_uint(Qg[(rq + 8) * 64 + c + 4]);
    }

    float oacc[8][4];
#pragma unroll
    for (int nt = 0; nt < 8; nt++)
#pragma unroll
        for (int i = 0; i < 4; i++) oacc[nt][i] = 0.f;
    float m_i[2] = {-INFINITY, -INFINITY};
    float l_i[2] = {0.f, 0.f};

    const int lkey = tid >> 4, lkd = (tid & 15) << 2;
    const int vkey = tid & 31, vd0 = (tid >> 5) << 2;

    for (int kt = 0; kt < LL / 32; kt++) {
        const int kb = kt << 5;
        __syncthreads();
#pragma unroll
        for (int p = 0; p < 2; p++) {
            float4 kv = *(const float4*)(Kg + (size_t)(kb + lkey + p * 16) * 64 + lkd);
            *(float4*)&Ks[(lkey + p * 16) * 68 + lkd] = kv;
        }
#pragma unroll
        for (int p = 0; p < 2; p++) {
            int d0 = vd0 + p * 32;
            float4 vv = *(const float4*)(Vg + (size_t)(kb + vkey) * 64 + d0);
            Vs[(d0 + 0) * 36 + vkey] = vv.x; Vs[(d0 + 1) * 36 + vkey] = vv.y;
            Vs[(d0 + 2) * 36 + vkey] = vv.z; Vs[(d0 + 3) * 36 + vkey] = vv.w;
        }
        __syncthreads();

        float sacc[4][4];
#pragma unroll
        for (int nt = 0; nt < 4; nt++)
#pragma unroll
            for (int i = 0; i < 4; i++) sacc[nt][i] = 0.f;
        const unsigned* Ku = (const unsigned*)Ks;
#pragma unroll
        for (int k = 0; k < 8; k++) {
            unsigned b[4][2];
#pragma unroll
            for (int nt = 0; nt < 4; nt++) {
                int bb = (nt * 8 + lr4) * 68 + k * 8 + lc;
                b[nt][0] = Ku[bb]; b[nt][1] = Ku[bb + 4];
            }
#pragma unroll
            for (int nt = 0; nt < 4; nt++) mma_tf32(sacc[nt], qf[k], b[nt]);
        }

#pragma unroll
        for (int h2 = 0; h2 < 2; h2++) {
            float rm = -INFINITY;
#pragma unroll
            for (int nt = 0; nt < 4; nt++)
                rm = fmaxf(rm, fmaxf(sacc[nt][h2 * 2], sacc[nt][h2 * 2 + 1]));
            rm = fmaxf(rm, __shfl_xor_sync(0xffffffffu, rm, 1));
            rm = fmaxf(rm, __shfl_xor_sync(0xffffffffu, rm, 2));
            float mn = fmaxf(m_i[h2], rm);
            float corr = __expf(m_i[h2] - mn);
            m_i[h2] = mn;
            float rs = 0.f;
#pragma unroll
            for (int nt = 0; nt < 4; nt++) {
                float p0 = __expf(sacc[nt][h2 * 2] - mn);
                float p1 = __expf(sacc[nt][h2 * 2 + 1] - mn);
                rs += p0 + p1;
                float2 pv;
                pv.x = __uint_as_float(f2tf32(p0));
                pv.y = __uint_as_float(f2tf32(p1));
                *(float2*)&Ps[(rq + h2 * 8) * 36 + nt * 8 + lc * 2] = pv;
            }
            rs += __shfl_xor_sync(0xffffffffu, rs, 1);
            rs += __shfl_xor_sync(0xffffffffu, rs, 2);
            l_i[h2] = l_i[h2] * corr + rs;
#pragma unroll
            for (int nt = 0; nt < 8; nt++) {
                oacc[nt][h2 * 2]     *= corr;
                oacc[nt][h2 * 2 + 1] *= corr;
            }
        }
        __syncwarp();

        const unsigned* Pu = (const unsigned*)Ps;
        const unsigned* Vu = (const unsigned*)Vs;
#pragma unroll
        for (int k = 0; k < 4; k++) {
            unsigned a[4];
            int ab = rq * 36 + k * 8 + lc;
            a[0] = Pu[ab];           a[1] = Pu[ab + 8 * 36];
            a[2] = Pu[ab + 4];       a[3] = Pu[ab + 8 * 36 + 4];
#pragma unroll
            for (int nt = 0; nt < 8; nt++) {
                unsigned b[2];
                int bb = (nt * 8 + lr4) * 36 + k * 8 + lc;
                b[0] = Vu[bb]; b[1] = Vu[bb + 4];
                mma_tf32(oacc[nt], a, b);
            }
        }
    }

    const int b = bh >> 4, h = bh & 15;
#pragma unroll
    for (int h2 = 0; h2 < 2; h2++) {
        int q = qbase + rq + h2 * 8;
        float sc = g_gate[b * LL + q] / l_i[h2];
        float* dst = g_o + ((size_t)(b * LL + q)) * DD + h * HD;
#pragma unroll
        for (int nt = 0; nt < 8; nt++) {
            int d = nt * 8 + lc * 2;
            float2 ov;
            ov.x = __uint_as_float(f2tf32(oacc[nt][h2 * 2] * sc));
            ov.y = __uint_as_float(f2tf32(oacc[nt][h2 * 2 + 1] * sc));
            *(float2*)(dst + d) = ov;
        }
    }
}

// ---------------------------------------------------------------------------
extern "C" void kernel_launch(void* const* d_in, const int* in_sizes, int n_in,
                              void* d_out, int out_size)
{
    const float* x    = (const float*)d_in[0];
    const float* G    = (const float*)d_in[1];
    const float* qkvw = (const float*)d_in[2];
    const float* outw = (const float*)d_in[3];
    const float* outb = (const float*)d_in[4];
    const float* gsc  = (const float*)d_in[5];
    const float* ltm  = (const float*)d_in[6];
    float* out = (float*)d_out;

    float* xt; cudaGetSymbolAddress((void**)&xt, g_xt);
    float* wq; cudaGetSymbolAddress((void**)&wq, g_wq);
    float* wo; cudaGetSymbolAddress((void**)&wo, g_wo);

    cvt_tf32_kernel<<<(MM * DD) / 256, 256>>>(x, xt, MM * DD);
    cvt_tf32_kernel<<<(N_QKV * DD) / 256, 256>>>(qkvw, wq, N_QKV * DD);
    cvt_tf32_kernel<<<(DD * DD) / 256, 256>>>(outw, wo, DD * DD);

    dim3 g1(N_QKV / 128, MM / 128);   // (24, 32)
    qkv_gemm_cp<<<g1, 256>>>();

    gate_kernel<<<BB, 256>>>(G, gsc, ltm);

    dim3 g2(LL / 128, BB * HH);       // (16, 32)
    attn_tc<<<g2, 256>>>();

    dim3 g3(DD / 128, MM / 128);      // (8, 32)
    out_gemm_cp<<<g3, 256>>>(outb, out);
}

// round 9
// speedup vs baseline: 1.3083x; 1.0617x over previous
#include <cuda_runtime.h>
#include <cstdint>
#include <math.h>

#define BB 2
#define LL 2048
#define DD 1024
#define HH 16
#define HD 64
#define MM (BB*LL)        // 4096
#define N_QKV (3*DD)      // 3072

// Scratch (allocation-free rule: __device__ globals)
__device__ float g_q[BB*HH*LL*HD];   // (b,h,l,d)  tf32-rounded, q pre-scaled by 1/8
__device__ float g_k[BB*HH*LL*HD];
__device__ float g_v[BB*HH*LL*HD];
__device__ float g_o[MM*DD];         // (b,l,h*64+d) tf32-rounded attention output
__device__ float g_gate[BB*LL];
__device__ float g_xt[MM*DD];        // tf32-rounded x
__device__ float g_wq[N_QKV*DD];     // tf32-rounded qkv_w
__device__ float g_wo[DD*DD];        // tf32-rounded out_w

// ---------------------------------------------------------------------------
// helpers
// ---------------------------------------------------------------------------
__device__ __forceinline__ unsigned f2tf32(float f) {
    unsigned u;
    asm("cvt.rna.tf32.f32 %0, %1;" : "=r"(u) : "f"(f));
    return u;
}

__device__ __forceinline__ void mma_tf32(float c[4], const unsigned a[4], const unsigned b[2]) {
    asm("mma.sync.aligned.m16n8k8.row.col.f32.tf32.tf32.f32 "
        "{%0,%1,%2,%3}, {%4,%5,%6,%7}, {%8,%9}, {%0,%1,%2,%3};"
        : "+f"(c[0]), "+f"(c[1]), "+f"(c[2]), "+f"(c[3])
        : "r"(a[0]), "r"(a[1]), "r"(a[2]), "r"(a[3]), "r"(b[0]), "r"(b[1]));
}

__device__ __forceinline__ uint32_t smem_u32(const void* p) {
    uint32_t a;
    asm("{ .reg .u64 t; cvta.to.shared.u64 t, %1; cvt.u32.u64 %0, t; }" : "=r"(a) : "l"(p));
    return a;
}

__device__ __forceinline__ void cp_async16(uint32_t dst, const void* src) {
    asm volatile("cp.async.cg.shared.global [%0], [%1], 16;" :: "r"(dst), "l"(src) : "memory");
}
#define CP_COMMIT() asm volatile("cp.async.commit_group;" ::: "memory")
#define CP_WAIT(n)  asm volatile("cp.async.wait_group %0;" :: "n"(n) : "memory")

// ---------------------------------------------------------------------------
// GEMM mainloop: 3-stage cp.async ring, K-slab 8, pad 12 (conflict-free:
// 12*lr4+lc distinct mod 32). One __syncthreads per slab, prefetch depth 2.
// Block 128x128, 256 threads / 8 warps, 64x32 warp tiles.
// Bit-identical accumulation order vs R8 (same k sequence).
// ---------------------------------------------------------------------------
#define SL_PAD 12
#define SBUF (128 * SL_PAD)

__device__ __forceinline__ void gemm_cp_main(
    const float* __restrict__ A, const float* __restrict__ W,
    int bm, int bn, float* As, float* Bs, float acc[4][4][4])
{
    const int tid = threadIdx.x, lane = tid & 31, wid = tid >> 5;
    const int wm = (wid & 1) << 6, wn = (wid >> 1) << 5;
    const int lr4 = lane >> 2, lc = lane & 3;

#pragma unroll
    for (int mt = 0; mt < 4; mt++)
#pragma unroll
        for (int nt = 0; nt < 4; nt++)
#pragma unroll
            for (int i = 0; i < 4; i++) acc[mt][nt][i] = 0.f;

    const int row = tid >> 1, col = (tid & 1) << 2;
    const float* Ag = A + (size_t)(bm + row) * DD + col;
    const float* Bg = W + (size_t)(bn + row) * DD + col;
    const uint32_t sA = smem_u32(As) + (row * SL_PAD + col) * 4;
    const uint32_t sB = smem_u32(Bs) + (row * SL_PAD + col) * 4;

    // prologue: slabs 0,1
    cp_async16(sA, Ag);                     cp_async16(sB, Bg);                     CP_COMMIT();
    cp_async16(sA + SBUF * 4, Ag + 8);      cp_async16(sB + SBUF * 4, Bg + 8);      CP_COMMIT();

    for (int slab = 0; slab < 128; slab++) {
        if (slab < 127) { CP_WAIT(1); } else { CP_WAIT(0); }
        __syncthreads();
        if (slab < 126) {
            const int nb = (slab + 2) % 3;
            const int g = (slab + 2) * 8;
            cp_async16(sA + nb * SBUF * 4, Ag + g);
            cp_async16(sB + nb * SBUF * 4, Bg + g);
            CP_COMMIT();
        }
        const unsigned* Au = (const unsigned*)(As + (slab % 3) * SBUF);
        const unsigned* Bu = (const unsigned*)(Bs + (slab % 3) * SBUF);
        unsigned a[4][4], b[4][2];
#pragma unroll
        for (int mt = 0; mt < 4; mt++) {
            int base = (wm + mt * 16 + lr4) * SL_PAD + lc;
            a[mt][0] = Au[base];      a[mt][1] = Au[base + 96];
            a[mt][2] = Au[base + 4];  a[mt][3] = Au[base + 100];
        }
#pragma unroll
        for (int nt = 0; nt < 4; nt++) {
            int bb = (wn + nt * 8 + lr4) * SL_PAD + lc;
            b[nt][0] = Bu[bb]; b[nt][1] = Bu[bb + 4];
        }
#pragma unroll
        for (int mt = 0; mt < 4; mt++)
#pragma unroll
            for (int nt = 0; nt < 4; nt++) mma_tf32(acc[mt][nt], a[mt], b[nt]);
    }
}

// ---------------------------------------------------------------------------
// QKV GEMM: M=4096, N=3072, K=1024. Grid (24, 32).
// Epilogue scatters tf32-rounded q(*0.125)/k/v into (b,h,l,d).
// ---------------------------------------------------------------------------
__device__ __forceinline__ void qkv_store(int m, int n, float v0, float v1) {
    int b = m >> 11, l = m & 2047;
    int which = n >> 10, h = (n >> 6) & 15, d = n & 63;
    float* dst = (which == 0) ? g_q : ((which == 1) ? g_k : g_v);
    if (which == 0) { v0 *= 0.125f; v1 *= 0.125f; }
    float2 val;
    val.x = __uint_as_float(f2tf32(v0));
    val.y = __uint_as_float(f2tf32(v1));
    *(float2*)(dst + ((size_t)((b << 4) + h) * LL + l) * HD + d) = val;
}

__global__ __launch_bounds__(256, 2) void qkv_gemm_cp() {
    __shared__ float As[3 * SBUF];
    __shared__ float Bs[3 * SBUF];
    const int bm = blockIdx.y << 7, bn = blockIdx.x << 7;
    const int lane = threadIdx.x & 31, wid = threadIdx.x >> 5;
    const int wm = (wid & 1) << 6, wn = (wid >> 1) << 5;
    const int lr4 = lane >> 2, lc = lane & 3;

    float acc[4][4][4];
    gemm_cp_main(g_xt, g_wq, bm, bn, As, Bs, acc);

#pragma unroll
    for (int mt = 0; mt < 4; mt++)
#pragma unroll
        for (int nt = 0; nt < 4; nt++) {
            int m = bm + wm + mt * 16 + lr4;
            int n = bn + wn + (nt << 3) + (lc << 1);
            qkv_store(m,     n, acc[mt][nt][0], acc[mt][nt][1]);
            qkv_store(m + 8, n, acc[mt][nt][2], acc[mt][nt][3]);
        }
}

// ---------------------------------------------------------------------------
// Out GEMM: M=4096, N=1024, K=1024. Grid (8, 32). + bias
// ---------------------------------------------------------------------------
__global__ __launch_bounds__(256, 2) void out_gemm_cp(
    const float* __restrict__ bias, float* __restrict__ C)
{
    __shared__ float As[3 * SBUF];
    __shared__ float Bs[3 * SBUF];
    const int bm = blockIdx.y << 7, bn = blockIdx.x << 7;
    const int lane = threadIdx.x & 31, wid = threadIdx.x >> 5;
    const int wm = (wid & 1) << 6, wn = (wid >> 1) << 5;
    const int lr4 = lane >> 2, lc = lane & 3;

    float acc[4][4][4];
    gemm_cp_main(g_o, g_wo, bm, bn, As, Bs, acc);

#pragma unroll
    for (int mt = 0; mt < 4; mt++)
#pragma unroll
        for (int nt = 0; nt < 4; nt++) {
            int m = bm + wm + mt * 16 + lr4;
            int n = bn + wn + (nt << 3) + (lc << 1);
            float2 r0v, r1v;
            r0v.x = acc[mt][nt][0] + bias[n];
            r0v.y = acc[mt][nt][1] + bias[n + 1];
            r1v.x = acc[mt][nt][2] + bias[n];
            r1v.y = acc[mt][nt][3] + bias[n + 1];
            *(float2*)&C[(size_t)m * DD + n]       = r0v;
            *(float2*)&C[(size_t)(m + 8) * DD + n] = r1v;
        }
}

// ---------------------------------------------------------------------------
// elementwise tf32 rounding
// ---------------------------------------------------------------------------
__global__ void cvt_tf32_kernel(const float* __restrict__ src, float* __restrict__ dst, int n) {
    int i = blockIdx.x * blockDim.x + threadIdx.x;
    if (i < n) dst[i] = __uint_as_float(f2tf32(src[i]));
}

// ---------------------------------------------------------------------------
// Gate: softmax over L of sqrt(Gr^2+Gi^2+eps)/temp, * gate_scale
// ---------------------------------------------------------------------------
__global__ __launch_bounds__(256) void gate_kernel(
    const float* __restrict__ G, const float* __restrict__ gs_p,
    const float* __restrict__ lt_p)
{
    __shared__ float sm[256];
    const int b = blockIdx.x, tid = threadIdx.x;
    const float inv_temp = __expf(-lt_p[0]);

    float z[8];
    float mx = -INFINITY;
#pragma unroll
    for (int i = 0; i < 8; i++) {
        int l = i * 256 + tid;
        float gr = G[(b * LL + l) * 2 + 0];
        float gi = G[(b * LL + l) * 2 + 1];
        z[i] = sqrtf(gr * gr + gi * gi + 1e-7f) * inv_temp;
        mx = fmaxf(mx, z[i]);
    }
    sm[tid] = mx; __syncthreads();
    for (int s = 128; s > 0; s >>= 1) {
        if (tid < s) sm[tid] = fmaxf(sm[tid], sm[tid + s]);
        __syncthreads();
    }
    const float gmax = sm[0];
    __syncthreads();

    float e[8]; float lsum = 0.f;
#pragma unroll
    for (int i = 0; i < 8; i++) { e[i] = __expf(z[i] - gmax); lsum += e[i]; }
    sm[tid] = lsum; __syncthreads();
    for (int s = 128; s > 0; s >>= 1) {
        if (tid < s) sm[tid] += sm[tid + s];
        __syncthreads();
    }
    const float inv_sum = 1.f / sm[0];
    const float gs = gs_p[0];
#pragma unroll
    for (int i = 0; i < 8; i++)
        g_gate[b * LL + i * 256 + tid] = e[i] * inv_sum * gs;
}

// ---------------------------------------------------------------------------
// Flash attention with cp.async pipelining.
// K double-buffered [2][32][68] ([key][d], pad 68: 4*lr4+lc conflict-free).
// V single buffer [32][72] un-transposed ([key][d], pad 72: 8*lc+lr4
// conflict-free for the PV B-fragment reads) -> cp.async fills it directly,
// no transpose STS. Commit order V-then-K so CP_WAIT(1) at f releases V
// while K(kt+1) is still in flight. V load overlaps S-GEMM+softmax;
// K(kt+1) load overlaps the whole iteration. 2 barriers/iter (unchanged).
// ---------------------------------------------------------------------------
__global__ __launch_bounds__(256, 2) void attn_cp() {
    __shared__ float Ks[2][32 * 68];
    __shared__ float Vs[32 * 72];
    __shared__ float Ps[128 * 36];

    const int tid = threadIdx.x, lane = tid & 31, wid = tid >> 5;
    const int bh = blockIdx.y, qbase = blockIdx.x << 7;
    const int lr4 = lane >> 2, lc = lane & 3;
    const int rq = wid * 16 + lr4;

    const float* Qg = g_q + ((size_t)bh * LL + qbase) * HD;
    const float* Kg = g_k + (size_t)bh * LL * HD;
    const float* Vg = g_v + (size_t)bh * LL * HD;

    // cp.async loader: thread covers key=tid>>3, cols kcol & kcol+32
    const int krow = tid >> 3;            // 0..31
    const int kcol = (tid & 7) << 2;      // 0..28
    const uint32_t dK0 = smem_u32(&Ks[0][0]) + (krow * 68 + kcol) * 4;
    const uint32_t dK1 = smem_u32(&Ks[1][0]) + (krow * 68 + kcol) * 4;
    const uint32_t dV  = smem_u32(Vs) + (krow * 72 + kcol) * 4;
    const float* Ksrc = Kg + krow * 64 + kcol;
    const float* Vsrc = Vg + krow * 64 + kcol;

    // Q fragments (already *0.125 and tf32-rounded by QKV epilogue)
    unsigned qf[8][4];
#pragma unroll
    for (int k = 0; k < 8; k++) {
        int c = k * 8 + lc;
        qf[k][0] = __float_as_uint(Qg[rq * 64 + c]);
        qf[k][1] = __float_as_uint(Qg[(rq + 8) * 64 + c]);
        qf[k][2] = __float_as_uint(Qg[rq * 64 + c + 4]);
        qf[k][3] = __float_as_uint(Qg[(rq + 8) * 64 + c + 4]);
    }

    float oacc[8][4];
#pragma unroll
    for (int nt = 0; nt < 8; nt++)
#pragma unroll
        for (int i = 0; i < 4; i++) oacc[nt][i] = 0.f;
    float m_i[2] = {-INFINITY, -INFINITY};
    float l_i[2] = {0.f, 0.f};

    // prologue: K tile 0 -> Ks[0]
    cp_async16(dK0, Ksrc); cp_async16(dK0 + 128, Ksrc + 32);
    CP_COMMIT();

    for (int kt = 0; kt < LL / 32; kt++) {
        const int buf = kt & 1;
        const int kb = kt << 5;

        CP_WAIT(0);            // K(kt) complete (sole pending group)
        __syncthreads();       // data visible; all warps done with prev iter

        // issue V(kt) (commit FIRST), then K(kt+1)
        cp_async16(dV, Vsrc + kb * 64); cp_async16(dV + 128, Vsrc + kb * 64 + 32);
        CP_COMMIT();
        if (kt < 63) {
            const float* ks2 = Ksrc + (kb + 32) * 64;
            const uint32_t dk = buf ? dK0 : dK1;
            cp_async16(dk, ks2); cp_async16(dk + 128, ks2 + 32);
            CP_COMMIT();
        }

        // S-GEMM on Ks[buf]
        float sacc[4][4];
#pragma unroll
        for (int nt = 0; nt < 4; nt++)
#pragma unroll
            for (int i = 0; i < 4; i++) sacc[nt][i] = 0.f;
        const unsigned* Ku = (const unsigned*)&Ks[buf][0];
#pragma unroll
        for (int k = 0; k < 8; k++) {
            unsigned b[4][2];
#pragma unroll
            for (int nt = 0; nt < 4; nt++) {
                int bb = (nt * 8 + lr4) * 68 + k * 8 + lc;
                b[nt][0] = Ku[bb]; b[nt][1] = Ku[bb + 4];
            }
#pragma unroll
            for (int nt = 0; nt < 4; nt++) mma_tf32(sacc[nt], qf[k], b[nt]);
        }

        // online softmax; stage tf32 P into per-warp smem rows
#pragma unroll
        for (int h2 = 0; h2 < 2; h2++) {
            float rm = -INFINITY;
#pragma unroll
            for (int nt = 0; nt < 4; nt++)
                rm = fmaxf(rm, fmaxf(sacc[nt][h2 * 2], sacc[nt][h2 * 2 + 1]));
            rm = fmaxf(rm, __shfl_xor_sync(0xffffffffu, rm, 1));
            rm = fmaxf(rm, __shfl_xor_sync(0xffffffffu, rm, 2));
            float mn = fmaxf(m_i[h2], rm);
            float corr = __expf(m_i[h2] - mn);
            m_i[h2] = mn;
            float rs = 0.f;
#pragma unroll
            for (int nt = 0; nt < 4; nt++) {
                float p0 = __expf(sacc[nt][h2 * 2] - mn);
                float p1 = __expf(sacc[nt][h2 * 2 + 1] - mn);
                rs += p0 + p1;
                float2 pv;
                pv.x = __uint_as_float(f2tf32(p0));
                pv.y = __uint_as_float(f2tf32(p1));
                *(float2*)&Ps[(rq + h2 * 8) * 36 + nt * 8 + lc * 2] = pv;
            }
            rs += __shfl_xor_sync(0xffffffffu, rs, 1);
            rs += __shfl_xor_sync(0xffffffffu, rs, 2);
            l_i[h2] = l_i[h2] * corr + rs;
#pragma unroll
            for (int nt = 0; nt < 8; nt++) {
                oacc[nt][h2 * 2]     *= corr;
                oacc[nt][h2 * 2 + 1] *= corr;
            }
        }

        if (kt < 63) { CP_WAIT(1); }   // V(kt) done; K(kt+1) may remain
        else         { CP_WAIT(0); }
        __syncthreads();               // Vs visible; Ps visible per-warp

        // O += P V  (Vs is [key][72] un-transposed)
        const unsigned* Pu = (const unsigned*)Ps;
        const unsigned* Vu = (const unsigned*)Vs;
#pragma unroll
        for (int k = 0; k < 4; k++) {
            unsigned a[4];
            int ab = rq * 36 + k * 8 + lc;
            a[0] = Pu[ab];           a[1] = Pu[ab + 8 * 36];
            a[2] = Pu[ab + 4];       a[3] = Pu[ab + 8 * 36 + 4];
#pragma unroll
            for (int nt = 0; nt < 8; nt++) {
                unsigned b[2];
                b[0] = Vu[(k * 8 + lc) * 72 + nt * 8 + lr4];
                b[1] = Vu[(k * 8 + lc + 4) * 72 + nt * 8 + lr4];
                mma_tf32(oacc[nt], a, b);
            }
        }
    }

    // Epilogue: 1/l, gate, tf32 round, scatter to (b, l, h*64+d)
    const int b = bh >> 4, h = bh & 15;
#pragma unroll
    for (int h2 = 0; h2 < 2; h2++) {
        int q = qbase + rq + h2 * 8;
        float sc = g_gate[b * LL + q] / l_i[h2];
        float* dst = g_o + ((size_t)(b * LL + q)) * DD + h * HD;
#pragma unroll
        for (int nt = 0; nt < 8; nt++) {
            int d = nt * 8 + lc * 2;
            float2 ov;
            ov.x = __uint_as_float(f2tf32(oacc[nt][h2 * 2] * sc));
            ov.y = __uint_as_float(f2tf32(oacc[nt][h2 * 2 + 1] * sc));
            *(float2*)(dst + d) = ov;
        }
    }
}

// ---------------------------------------------------------------------------
extern "C" void kernel_launch(void* const* d_in, const int* in_sizes, int n_in,
                              void* d_out, int out_size)
{
    const float* x    = (const float*)d_in[0];
    const float* G    = (const float*)d_in[1];
    const float* qkvw = (const float*)d_in[2];
    const float* outw = (const float*)d_in[3];
    const float* outb = (const float*)d_in[4];
    const float* gsc  = (const float*)d_in[5];
    const float* ltm  = (const float*)d_in[6];
    float* out = (float*)d_out;

    float* xt; cudaGetSymbolAddress((void**)&xt, g_xt);
    float* wq; cudaGetSymbolAddress((void**)&wq, g_wq);
    float* wo; cudaGetSymbolAddress((void**)&wo, g_wo);

    cvt_tf32_kernel<<<(MM * DD) / 256, 256>>>(x, xt, MM * DD);
    cvt_tf32_kernel<<<(N_QKV * DD) / 256, 256>>>(qkvw, wq, N_QKV * DD);
    cvt_tf32_kernel<<<(DD * DD) / 256, 256>>>(outw, wo, DD * DD);

    dim3 g1(N_QKV / 128, MM / 128);   // (24, 32)
    qkv_gemm_cp<<<g1, 256>>>();

    gate_kernel<<<BB, 256>>>(G, gsc, ltm);

    dim3 g2(LL / 128, BB * HH);       // (16, 32)
    attn_cp<<<g2, 256>>>();

    dim3 g3(DD / 128, MM / 128);      // (8, 32)
    out_gemm_cp<<<g3, 256>>>(outb, out);
}

// round 10
// speedup vs baseline: 1.4246x; 1.0889x over previous
#include <cuda_runtime.h>
#include <cstdint>
#include <math.h>

#define BB 2
#define LL 2048
#define DD 1024
#define HH 16
#define HD 64
#define MM (BB*LL)        // 4096
#define N_QKV (3*DD)      // 3072

// Scratch (allocation-free rule: __device__ globals)
__device__ float g_q[BB*HH*LL*HD];   // (b,h,l,d)  tf32-rounded, q pre-scaled by 1/8
__device__ float g_k[BB*HH*LL*HD];
__device__ float g_v[BB*HH*LL*HD];
__device__ float g_o[MM*DD];         // (b,l,h*64+d) tf32-rounded attention output
__device__ float g_gate[BB*LL];
__device__ float g_xt[MM*DD];        // tf32-rounded x
__device__ float g_wq[N_QKV*DD];     // tf32-rounded qkv_w
__device__ float g_wo[DD*DD];        // tf32-rounded out_w

// ---------------------------------------------------------------------------
// helpers
// ---------------------------------------------------------------------------
__device__ __forceinline__ unsigned f2tf32(float f) {
    unsigned u;
    asm("cvt.rna.tf32.f32 %0, %1;" : "=r"(u) : "f"(f));
    return u;
}

__device__ __forceinline__ void mma_tf32(float c[4], const unsigned a[4], const unsigned b[2]) {
    asm("mma.sync.aligned.m16n8k8.row.col.f32.tf32.tf32.f32 "
        "{%0,%1,%2,%3}, {%4,%5,%6,%7}, {%8,%9}, {%0,%1,%2,%3};"
        : "+f"(c[0]), "+f"(c[1]), "+f"(c[2]), "+f"(c[3])
        : "r"(a[0]), "r"(a[1]), "r"(a[2]), "r"(a[3]), "r"(b[0]), "r"(b[1]));
}

__device__ __forceinline__ uint32_t smem_u32(const void* p) {
    uint32_t a;
    asm("{ .reg .u64 t; cvta.to.shared.u64 t, %1; cvt.u32.u64 %0, t; }" : "=r"(a) : "l"(p));
    return a;
}

__device__ __forceinline__ void cp_async16(uint32_t dst, const void* src) {
    asm volatile("cp.async.cg.shared.global [%0], [%1], 16;" :: "r"(dst), "l"(src) : "memory");
}
#define CP_COMMIT() asm volatile("cp.async.commit_group;" ::: "memory")
#define CP_WAIT(n)  asm volatile("cp.async.wait_group %0;" :: "n"(n) : "memory")

// ---------------------------------------------------------------------------
// GEMM mainloop: R8-proven geometry. 2-stage cp.async double buffer,
// K-slab 16, pad 20 (conflict-free). Block 128x128, 256 threads / 8 warps,
// 64x32 warp tiles. Buffer index = slab&1 (no modulo). 232us / tensor 41%.
// ---------------------------------------------------------------------------
#define BUF_FLOATS (128 * 20)

__device__ __forceinline__ void gemm_cp_main(
    const float* __restrict__ A, const float* __restrict__ W,
    int bm, int bn, float* As, float* Bs, float acc[4][4][4])
{
    const int tid = threadIdx.x, lane = tid & 31, wid = tid >> 5;
    const int wm = (wid & 1) << 6, wn = (wid >> 1) << 5;
    const int lr4 = lane >> 2, lc = lane & 3;

#pragma unroll
    for (int mt = 0; mt < 4; mt++)
#pragma unroll
        for (int nt = 0; nt < 4; nt++)
#pragma unroll
            for (int i = 0; i < 4; i++) acc[mt][nt][i] = 0.f;

    const int row = tid >> 2, kk = (tid & 3) << 2;
    const float* Ag0 = A + (size_t)(bm + row) * DD + kk;
    const float* Ag1 = Ag0 + (size_t)64 * DD;
    const float* Bg0 = W + (size_t)(bn + row) * DD + kk;
    const float* Bg1 = Bg0 + (size_t)64 * DD;
    const uint32_t sA = smem_u32(As), sB = smem_u32(Bs);
    const uint32_t dA0 = sA + (row * 20 + kk) * 4;
    const uint32_t dA1 = sA + ((row + 64) * 20 + kk) * 4;
    const uint32_t dB0 = sB + (row * 20 + kk) * 4;
    const uint32_t dB1 = sB + ((row + 64) * 20 + kk) * 4;

    // prologue: slab 0 -> buf 0
    cp_async16(dA0, Ag0); cp_async16(dA1, Ag1);
    cp_async16(dB0, Bg0); cp_async16(dB1, Bg1);
    CP_COMMIT();

    for (int slab = 0; slab < 64; slab++) {
        const int buf = slab & 1;
        if (slab < 63) {
            const uint32_t off = (uint32_t)(buf ^ 1) * (BUF_FLOATS * 4);
            const int g = (slab + 1) * 16;
            cp_async16(dA0 + off, Ag0 + g); cp_async16(dA1 + off, Ag1 + g);
            cp_async16(dB0 + off, Bg0 + g); cp_async16(dB1 + off, Bg1 + g);
            CP_COMMIT();
            CP_WAIT(1);      // slab's own group complete
        } else {
            CP_WAIT(0);
        }
        __syncthreads();

        const unsigned* Au = (const unsigned*)(As + buf * BUF_FLOATS);
        const unsigned* Bu = (const unsigned*)(Bs + buf * BUF_FLOATS);
#pragma unroll
        for (int ks = 0; ks < 16; ks += 8) {
            unsigned a[4][4], b[4][2];
#pragma unroll
            for (int mt = 0; mt < 4; mt++) {
                int base = (wm + mt * 16 + lr4) * 20 + ks + lc;
                a[mt][0] = Au[base];       a[mt][1] = Au[base + 160];
                a[mt][2] = Au[base + 4];   a[mt][3] = Au[base + 164];
            }
#pragma unroll
            for (int nt = 0; nt < 4; nt++) {
                int bb = (wn + nt * 8 + lr4) * 20 + ks + lc;
                b[nt][0] = Bu[bb]; b[nt][1] = Bu[bb + 4];
            }
#pragma unroll
            for (int mt = 0; mt < 4; mt++)
#pragma unroll
                for (int nt = 0; nt < 4; nt++) mma_tf32(acc[mt][nt], a[mt], b[nt]);
        }
        __syncthreads();   // all warps done with buf before it is refilled
    }
}

// ---------------------------------------------------------------------------
// QKV GEMM: M=4096, N=3072, K=1024. Grid (24, 32).
// Epilogue scatters tf32-rounded q(*0.125)/k/v into (b,h,l,d).
// ---------------------------------------------------------------------------
__device__ __forceinline__ void qkv_store(int m, int n, float v0, float v1) {
    int b = m >> 11, l = m & 2047;
    int which = n >> 10, h = (n >> 6) & 15, d = n & 63;
    float* dst = (which == 0) ? g_q : ((which == 1) ? g_k : g_v);
    if (which == 0) { v0 *= 0.125f; v1 *= 0.125f; }
    float2 val;
    val.x = __uint_as_float(f2tf32(v0));
    val.y = __uint_as_float(f2tf32(v1));
    *(float2*)(dst + ((size_t)((b << 4) + h) * LL + l) * HD + d) = val;
}

__global__ __launch_bounds__(256, 2) void qkv_gemm_cp() {
    __shared__ float As[2 * BUF_FLOATS];
    __shared__ float Bs[2 * BUF_FLOATS];
    const int bm = blockIdx.y << 7, bn = blockIdx.x << 7;
    const int lane = threadIdx.x & 31, wid = threadIdx.x >> 5;
    const int wm = (wid & 1) << 6, wn = (wid >> 1) << 5;
    const int lr4 = lane >> 2, lc = lane & 3;

    float acc[4][4][4];
    gemm_cp_main(g_xt, g_wq, bm, bn, As, Bs, acc);

#pragma unroll
    for (int mt = 0; mt < 4; mt++)
#pragma unroll
        for (int nt = 0; nt < 4; nt++) {
            int m = bm + wm + mt * 16 + lr4;
            int n = bn + wn + (nt << 3) + (lc << 1);
            qkv_store(m,     n, acc[mt][nt][0], acc[mt][nt][1]);
            qkv_store(m + 8, n, acc[mt][nt][2], acc[mt][nt][3]);
        }
}

// ---------------------------------------------------------------------------
// Out GEMM: M=4096, N=1024, K=1024. Grid (8, 32). + bias
// ---------------------------------------------------------------------------
__global__ __launch_bounds__(256, 2) void out_gemm_cp(
    const float* __restrict__ bias, float* __restrict__ C)
{
    __shared__ float As[2 * BUF_FLOATS];
    __shared__ float Bs[2 * BUF_FLOATS];
    const int bm = blockIdx.y << 7, bn = blockIdx.x << 7;
    const int lane = threadIdx.x & 31, wid = threadIdx.x >> 5;
    const int wm = (wid & 1) << 6, wn = (wid >> 1) << 5;
    const int lr4 = lane >> 2, lc = lane & 3;

    float acc[4][4][4];
    gemm_cp_main(g_o, g_wo, bm, bn, As, Bs, acc);

#pragma unroll
    for (int mt = 0; mt < 4; mt++)
#pragma unroll
        for (int nt = 0; nt < 4; nt++) {
            int m = bm + wm + mt * 16 + lr4;
            int n = bn + wn + (nt << 3) + (lc << 1);
            float2 r0v, r1v;
            r0v.x = acc[mt][nt][0] + bias[n];
            r0v.y = acc[mt][nt][1] + bias[n + 1];
            r1v.x = acc[mt][nt][2] + bias[n];
            r1v.y = acc[mt][nt][3] + bias[n + 1];
            *(float2*)&C[(size_t)m * DD + n]       = r0v;
            *(float2*)&C[(size_t)(m + 8) * DD + n] = r1v;
        }
}

// ---------------------------------------------------------------------------
// elementwise tf32 rounding
// ---------------------------------------------------------------------------
__global__ void cvt_tf32_kernel(const float* __restrict__ src, float* __restrict__ dst, int n) {
    int i = blockIdx.x * blockDim.x + threadIdx.x;
    if (i < n) dst[i] = __uint_as_float(f2tf32(src[i]));
}

// ---------------------------------------------------------------------------
// Gate: softmax over L of sqrt(Gr^2+Gi^2+eps)/temp, * gate_scale
// ---------------------------------------------------------------------------
__global__ __launch_bounds__(256) void gate_kernel(
    const float* __restrict__ G, const float* __restrict__ gs_p,
    const float* __restrict__ lt_p)
{
    __shared__ float sm[256];
    const int b = blockIdx.x, tid = threadIdx.x;
    const float inv_temp = __expf(-lt_p[0]);

    float z[8];
    float mx = -INFINITY;
#pragma unroll
    for (int i = 0; i < 8; i++) {
        int l = i * 256 + tid;
        float gr = G[(b * LL + l) * 2 + 0];
        float gi = G[(b * LL + l) * 2 + 1];
        z[i] = sqrtf(gr * gr + gi * gi + 1e-7f) * inv_temp;
        mx = fmaxf(mx, z[i]);
    }
    sm[tid] = mx; __syncthreads();
    for (int s = 128; s > 0; s >>= 1) {
        if (tid < s) sm[tid] = fmaxf(sm[tid], sm[tid + s]);
        __syncthreads();
    }
    const float gmax = sm[0];
    __syncthreads();

    float e[8]; float lsum = 0.f;
#pragma unroll
    for (int i = 0; i < 8; i++) { e[i] = __expf(z[i] - gmax); lsum += e[i]; }
    sm[tid] = lsum; __syncthreads();
    for (int s = 128; s > 0; s >>= 1) {
        if (tid < s) sm[tid] += sm[tid + s];
        __syncthreads();
    }
    const float inv_sum = 1.f / sm[0];
    const float gs = gs_p[0];
#pragma unroll
    for (int i = 0; i < 8; i++)
        g_gate[b * LL + i * 256 + tid] = e[i] * inv_sum * gs;
}

// ---------------------------------------------------------------------------
// Flash attention with cp.async pipelining (R9-proven, unchanged).
// K double-buffered [2][32][68]; V single [32][72] un-transposed;
// commit order V-then-K so CP_WAIT(1) releases V while K(kt+1) in flight.
// ---------------------------------------------------------------------------
__global__ __launch_bounds__(256, 2) void attn_cp() {
    __shared__ float Ks[2][32 * 68];
    __shared__ float Vs[32 * 72];
    __shared__ float Ps[128 * 36];

    const int tid = threadIdx.x, lane = tid & 31, wid = tid >> 5;
    const int bh = blockIdx.y, qbase = blockIdx.x << 7;
    const int lr4 = lane >> 2, lc = lane & 3;
    const int rq = wid * 16 + lr4;

    const float* Qg = g_q + ((size_t)bh * LL + qbase) * HD;
    const float* Kg = g_k + (size_t)bh * LL * HD;
    const float* Vg = g_v + (size_t)bh * LL * HD;

    const int krow = tid >> 3;            // 0..31
    const int kcol = (tid & 7) << 2;      // 0..28
    const uint32_t dK0 = smem_u32(&Ks[0][0]) + (krow * 68 + kcol) * 4;
    const uint32_t dK1 = smem_u32(&Ks[1][0]) + (krow * 68 + kcol) * 4;
    const uint32_t dV  = smem_u32(Vs) + (krow * 72 + kcol) * 4;
    const float* Ksrc = Kg + krow * 64 + kcol;
    const float* Vsrc = Vg + krow * 64 + kcol;

    unsigned qf[8][4];
#pragma unroll
    for (int k = 0; k < 8; k++) {
        int c = k * 8 + lc;
        qf[k][0] = __float_as_uint(Qg[rq * 64 + c]);
        qf[k][1] = __float_as_uint(Qg[(rq + 8) * 64 + c]);
        qf[k][2] = __float_as_uint(Qg[rq * 64 + c + 4]);
        qf[k][3] = __float_as_uint(Qg[(rq + 8) * 64 + c + 4]);
    }

    float oacc[8][4];
#pragma unroll
    for (int nt = 0; nt < 8; nt++)
#pragma unroll
        for (int i = 0; i < 4; i++) oacc[nt][i] = 0.f;
    float m_i[2] = {-INFINITY, -INFINITY};
    float l_i[2] = {0.f, 0.f};

    // prologue: K tile 0 -> Ks[0]
    cp_async16(dK0, Ksrc); cp_async16(dK0 + 128, Ksrc + 32);
    CP_COMMIT();

    for (int kt = 0; kt < LL / 32; kt++) {
        const int buf = kt & 1;
        const int kb = kt << 5;

        CP_WAIT(0);            // K(kt) complete (sole pending group)
        __syncthreads();       // data visible; all warps done with prev iter

        // issue V(kt) (commit FIRST), then K(kt+1)
        cp_async16(dV, Vsrc + kb * 64); cp_async16(dV + 128, Vsrc + kb * 64 + 32);
        CP_COMMIT();
        if (kt < 63) {
            const float* ks2 = Ksrc + (kb + 32) * 64;
            const uint32_t dk = buf ? dK0 : dK1;
            cp_async16(dk, ks2); cp_async16(dk + 128, ks2 + 32);
            CP_COMMIT();
        }

        // S-GEMM on Ks[buf]
        float sacc[4][4];
#pragma unroll
        for (int nt = 0; nt < 4; nt++)
#pragma unroll
            for (int i = 0; i < 4; i++) sacc[nt][i] = 0.f;
        const unsigned* Ku = (const unsigned*)&Ks[buf][0];
#pragma unroll
        for (int k = 0; k < 8; k++) {
            unsigned b[4][2];
#pragma unroll
            for (int nt = 0; nt < 4; nt++) {
                int bb = (nt * 8 + lr4) * 68 + k * 8 + lc;
                b[nt][0] = Ku[bb]; b[nt][1] = Ku[bb + 4];
            }
#pragma unroll
            for (int nt = 0; nt < 4; nt++) mma_tf32(sacc[nt], qf[k], b[nt]);
        }

        // online softmax; stage tf32 P into per-warp smem rows
#pragma unroll
        for (int h2 = 0; h2 < 2; h2++) {
            float rm = -INFINITY;
#pragma unroll
            for (int nt = 0; nt < 4; nt++)
                rm = fmaxf(rm, fmaxf(sacc[nt][h2 * 2], sacc[nt][h2 * 2 + 1]));
            rm = fmaxf(rm, __shfl_xor_sync(0xffffffffu, rm, 1));
            rm = fmaxf(rm, __shfl_xor_sync(0xffffffffu, rm, 2));
            float mn = fmaxf(m_i[h2], rm);
            float corr = __expf(m_i[h2] - mn);
            m_i[h2] = mn;
            float rs = 0.f;
#pragma unroll
            for (int nt = 0; nt < 4; nt++) {
                float p0 = __expf(sacc[nt][h2 * 2] - mn);
                float p1 = __expf(sacc[nt][h2 * 2 + 1] - mn);
                rs += p0 + p1;
                float2 pv;
                pv.x = __uint_as_float(f2tf32(p0));
                pv.y = __uint_as_float(f2tf32(p1));
                *(float2*)&Ps[(rq + h2 * 8) * 36 + nt * 8 + lc * 2] = pv;
            }
            rs += __shfl_xor_sync(0xffffffffu, rs, 1);
            rs += __shfl_xor_sync(0xffffffffu, rs, 2);
            l_i[h2] = l_i[h2] * corr + rs;
#pragma unroll
            for (int nt = 0; nt < 8; nt++) {
                oacc[nt][h2 * 2]     *= corr;
                oacc[nt][h2 * 2 + 1] *= corr;
            }
        }

        if (kt < 63) { CP_WAIT(1); }   // V(kt) done; K(kt+1) may remain
        else         { CP_WAIT(0); }
        __syncthreads();               // Vs visible; Ps visible per-warp

        // O += P V  (Vs is [key][72] un-transposed)
        const unsigned* Pu = (const unsigned*)Ps;
        const unsigned* Vu = (const unsigned*)Vs;
#pragma unroll
        for (int k = 0; k < 4; k++) {
            unsigned a[4];
            int ab = rq * 36 + k * 8 + lc;
            a[0] = Pu[ab];           a[1] = Pu[ab + 8 * 36];
            a[2] = Pu[ab + 4];       a[3] = Pu[ab + 8 * 36 + 4];
#pragma unroll
            for (int nt = 0; nt < 8; nt++) {
                unsigned b[2];
                b[0] = Vu[(k * 8 + lc) * 72 + nt * 8 + lr4];
                b[1] = Vu[(k * 8 + lc + 4) * 72 + nt * 8 + lr4];
                mma_tf32(oacc[nt], a, b);
            }
        }
    }

    // Epilogue: 1/l, gate, tf32 round, scatter to (b, l, h*64+d)
    const int b = bh >> 4, h = bh & 15;
#pragma unroll
    for (int h2 = 0; h2 < 2; h2++) {
        int q = qbase + rq + h2 * 8;
        float sc = g_gate[b * LL + q] / l_i[h2];
        float* dst = g_o + ((size_t)(b * LL + q)) * DD + h * HD;
#pragma unroll
        for (int nt = 0; nt < 8; nt++) {
            int d = nt * 8 + lc * 2;
            float2 ov;
            ov.x = __uint_as_float(f2tf32(oacc[nt][h2 * 2] * sc));
            ov.y = __uint_as_float(f2tf32(oacc[nt][h2 * 2 + 1] * sc));
            *(float2*)(dst + d) = ov;
        }
    }
}

// ---------------------------------------------------------------------------
extern "C" void kernel_launch(void* const* d_in, const int* in_sizes, int n_in,
                              void* d_out, int out_size)
{
    const float* x    = (const float*)d_in[0];
    const float* G    = (const float*)d_in[1];
    const float* qkvw = (const float*)d_in[2];
    const float* outw = (const float*)d_in[3];
    const float* outb = (const float*)d_in[4];
    const float* gsc  = (const float*)d_in[5];
    const float* ltm  = (const float*)d_in[6];
    float* out = (float*)d_out;

    float* xt; cudaGetSymbolAddress((void**)&xt, g_xt);
    float* wq; cudaGetSymbolAddress((void**)&wq, g_wq);
    float* wo; cudaGetSymbolAddress((void**)&wo, g_wo);

    cvt_tf32_kernel<<<(MM * DD) / 256, 256>>>(x, xt, MM * DD);
    cvt_tf32_kernel<<<(N_QKV * DD) / 256, 256>>>(qkvw, wq, N_QKV * DD);
    cvt_tf32_kernel<<<(DD * DD) / 256, 256>>>(outw, wo, DD * DD);

    dim3 g1(N_QKV / 128, MM / 128);   // (24, 32)
    qkv_gemm_cp<<<g1, 256>>>();

    gate_kernel<<<BB, 256>>>(G, gsc, ltm);

    dim3 g2(LL / 128, BB * HH);       // (16, 32)
    attn_cp<<<g2, 256>>>();

    dim3 g3(DD / 128, MM / 128);      // (8, 32)
    out_gemm_cp<<<g3, 256>>>(outb, out);
}

// round 11
// speedup vs baseline: 1.5189x; 1.0662x over previous
#include <cuda_runtime.h>
#include <cstdint>
#include <math.h>

#define BB 2
#define LL 2048
#define DD 1024
#define HH 16
#define HD 64
#define MM (BB*LL)        // 4096
#define N_QKV (3*DD)      // 3072

// Scratch (allocation-free rule: __device__ globals)
__device__ float g_q[BB*HH*LL*HD];   // (b,h,l,d)  tf32-rounded, q pre-scaled by 1/8
__device__ float g_k[BB*HH*LL*HD];   // (b,h,l,d)  tf32-rounded
__device__ float g_vt[BB*HH*HD*LL];  // (b,h,d,l)  V TRANSPOSED, tf32-rounded
__device__ float g_o[MM*DD];         // (b,l,h*64+d) tf32-rounded attention output
__device__ float g_gate[BB*LL];
__device__ float g_xt[MM*DD];        // tf32-rounded x
__device__ float g_wq[N_QKV*DD];     // tf32-rounded qkv_w
__device__ float g_wo[DD*DD];        // tf32-rounded out_w

// ---------------------------------------------------------------------------
// helpers
// ---------------------------------------------------------------------------
__device__ __forceinline__ unsigned f2tf32(float f) {
    unsigned u;
    asm("cvt.rna.tf32.f32 %0, %1;" : "=r"(u) : "f"(f));
    return u;
}

__device__ __forceinline__ void mma_tf32(float c[4], const unsigned a[4], const unsigned b[2]) {
    asm("mma.sync.aligned.m16n8k8.row.col.f32.tf32.tf32.f32 "
        "{%0,%1,%2,%3}, {%4,%5,%6,%7}, {%8,%9}, {%0,%1,%2,%3};"
        : "+f"(c[0]), "+f"(c[1]), "+f"(c[2]), "+f"(c[3])
        : "r"(a[0]), "r"(a[1]), "r"(a[2]), "r"(a[3]), "r"(b[0]), "r"(b[1]));
}

__device__ __forceinline__ uint32_t smem_u32(const void* p) {
    uint32_t a;
    asm("{ .reg .u64 t; cvta.to.shared.u64 t, %1; cvt.u32.u64 %0, t; }" : "=r"(a) : "l"(p));
    return a;
}

__device__ __forceinline__ void cp_async16(uint32_t dst, const void* src) {
    asm volatile("cp.async.cg.shared.global [%0], [%1], 16;" :: "r"(dst), "l"(src) : "memory");
}
#define CP_COMMIT() asm volatile("cp.async.commit_group;" ::: "memory")
#define CP_WAIT(n)  asm volatile("cp.async.wait_group %0;" :: "n"(n) : "memory")

// ldmatrix x4 on tf32 data (bit-transparent through .b16): 4 8x8-b16 blocks.
// x1 mapping: thread t <- block element [t>>2][t&3] (as tf32). Non-trans only.
#define LDSM4(r0, r1, r2, r3, addr) \
    asm volatile("ldmatrix.sync.aligned.m8n8.x4.shared.b16 {%0,%1,%2,%3}, [%4];" \
        : "=r"(r0), "=r"(r1), "=r"(r2), "=r"(r3) : "r"(addr))

// ---------------------------------------------------------------------------
// GEMM mainloop: R8/R10-proven pipeline (2-stage cp.async, K-slab 16, pad 20,
// 256 thr / 8 warps, 64x32 warp tiles) with ldmatrix fragment loads:
// per k-step A: 4 LDSM.x4 (was 16 LDS.32), B: 2 LDSM.x4 (was 8 LDS.32).
// Accumulation order bit-identical to R10.
// ---------------------------------------------------------------------------
#define BUF_FLOATS (128 * 20)

__device__ __forceinline__ void gemm_cp_main(
    const float* __restrict__ A, const float* __restrict__ W,
    int bm, int bn, float* As, float* Bs, float acc[4][4][4])
{
    const int tid = threadIdx.x, lane = tid & 31, wid = tid >> 5;
    const int wm = (wid & 1) << 6, wn = (wid >> 1) << 5;

#pragma unroll
    for (int mt = 0; mt < 4; mt++)
#pragma unroll
        for (int nt = 0; nt < 4; nt++)
#pragma unroll
            for (int i = 0; i < 4; i++) acc[mt][nt][i] = 0.f;

    // cp.async loader addressing (unchanged)
    const int row = tid >> 2, kk = (tid & 3) << 2;
    const float* Ag0 = A + (size_t)(bm + row) * DD + kk;
    const float* Ag1 = Ag0 + (size_t)64 * DD;
    const float* Bg0 = W + (size_t)(bn + row) * DD + kk;
    const float* Bg1 = Bg0 + (size_t)64 * DD;
    const uint32_t sA = smem_u32(As), sB = smem_u32(Bs);
    const uint32_t dA0 = sA + (row * 20 + kk) * 4;
    const uint32_t dA1 = sA + ((row + 64) * 20 + kk) * 4;
    const uint32_t dB0 = sB + (row * 20 + kk) * 4;
    const uint32_t dB1 = sB + ((row + 64) * 20 + kk) * 4;

    // ldmatrix row addresses (per thread; j = lane>>3 selects block)
    const int r8 = lane & 7, j = lane >> 3;
    const int jm = (j & 1) << 3, jk = (j >> 1) << 2;   // A: blocks (m|m+8) x (k|k+4)
    const int jn = (j >> 1) << 3, jk2 = (j & 1) << 2;  // B: blocks (n|n+8) x (k|k+4)
    uint32_t aAddr[4], bAddr[2];
#pragma unroll
    for (int mt = 0; mt < 4; mt++)
        aAddr[mt] = sA + 4u * ((wm + mt * 16 + jm + r8) * 20 + jk);
#pragma unroll
    for (int p = 0; p < 2; p++)
        bAddr[p] = sB + 4u * ((wn + p * 16 + jn + r8) * 20 + jk2);

    // prologue: slab 0 -> buf 0
    cp_async16(dA0, Ag0); cp_async16(dA1, Ag1);
    cp_async16(dB0, Bg0); cp_async16(dB1, Bg1);
    CP_COMMIT();

    for (int slab = 0; slab < 64; slab++) {
        const int buf = slab & 1;
        if (slab < 63) {
            const uint32_t off = (uint32_t)(buf ^ 1) * (BUF_FLOATS * 4);
            const int g = (slab + 1) * 16;
            cp_async16(dA0 + off, Ag0 + g); cp_async16(dA1 + off, Ag1 + g);
            cp_async16(dB0 + off, Bg0 + g); cp_async16(dB1 + off, Bg1 + g);
            CP_COMMIT();
            CP_WAIT(1);
        } else {
            CP_WAIT(0);
        }
        __syncthreads();

        const uint32_t bufoff = (uint32_t)buf * (BUF_FLOATS * 4);
#pragma unroll
        for (int ks = 0; ks < 2; ks++) {
            const uint32_t off = bufoff + (uint32_t)ks * 32;  // +8 words per k-step
            unsigned a[4][4], bb[2][4];
#pragma unroll
            for (int mt = 0; mt < 4; mt++)
                LDSM4(a[mt][0], a[mt][1], a[mt][2], a[mt][3], aAddr[mt] + off);
            LDSM4(bb[0][0], bb[0][1], bb[0][2], bb[0][3], bAddr[0] + off);
            LDSM4(bb[1][0], bb[1][1], bb[1][2], bb[1][3], bAddr[1] + off);
#pragma unroll
            for (int mt = 0; mt < 4; mt++)
#pragma unroll
                for (int nt = 0; nt < 4; nt++)
                    mma_tf32(acc[mt][nt], a[mt], &bb[nt >> 1][(nt & 1) << 1]);
        }
        __syncthreads();
    }
}

// ---------------------------------------------------------------------------
// QKV GEMM: M=4096, N=3072, K=1024. Grid (24, 32).
// Epilogue: q scaled 1/8 -> g_q (b,h,l,d); k -> g_k (b,h,l,d);
//           v -> g_vt TRANSPOSED (b,h,d,l). All tf32-rounded.
// ---------------------------------------------------------------------------
__device__ __forceinline__ void qkv_store(int m, int n, float v0, float v1) {
    int b = m >> 11, l = m & 2047;
    int which = n >> 10, h = (n >> 6) & 15, d = n & 63;
    int bh = (b << 4) + h;
    if (which == 2) {
        float* dst = g_vt + ((size_t)(bh * 64 + d)) * LL + l;
        dst[0]  = __uint_as_float(f2tf32(v0));
        dst[LL] = __uint_as_float(f2tf32(v1));   // d+1 row
        return;
    }
    float* dst = (which == 0) ? g_q : g_k;
    if (which == 0) { v0 *= 0.125f; v1 *= 0.125f; }
    float2 val;
    val.x = __uint_as_float(f2tf32(v0));
    val.y = __uint_as_float(f2tf32(v1));
    *(float2*)(dst + ((size_t)bh * LL + l) * HD + d) = val;
}

__global__ __launch_bounds__(256, 2) void qkv_gemm_cp() {
    __shared__ float As[2 * BUF_FLOATS];
    __shared__ float Bs[2 * BUF_FLOATS];
    const int bm = blockIdx.y << 7, bn = blockIdx.x << 7;
    const int lane = threadIdx.x & 31, wid = threadIdx.x >> 5;
    const int wm = (wid & 1) << 6, wn = (wid >> 1) << 5;
    const int lr4 = lane >> 2, lc = lane & 3;

    float acc[4][4][4];
    gemm_cp_main(g_xt, g_wq, bm, bn, As, Bs, acc);

#pragma unroll
    for (int mt = 0; mt < 4; mt++)
#pragma unroll
        for (int nt = 0; nt < 4; nt++) {
            int m = bm + wm + mt * 16 + lr4;
            int n = bn + wn + (nt << 3) + (lc << 1);
            qkv_store(m,     n, acc[mt][nt][0], acc[mt][nt][1]);
            qkv_store(m + 8, n, acc[mt][nt][2], acc[mt][nt][3]);
        }
}

// ---------------------------------------------------------------------------
// Out GEMM: M=4096, N=1024, K=1024. Grid (8, 32). + bias
// ---------------------------------------------------------------------------
__global__ __launch_bounds__(256, 2) void out_gemm_cp(
    const float* __restrict__ bias, float* __restrict__ C)
{
    __shared__ float As[2 * BUF_FLOATS];
    __shared__ float Bs[2 * BUF_FLOATS];
    const int bm = blockIdx.y << 7, bn = blockIdx.x << 7;
    const int lane = threadIdx.x & 31, wid = threadIdx.x >> 5;
    const int wm = (wid & 1) << 6, wn = (wid >> 1) << 5;
    const int lr4 = lane >> 2, lc = lane & 3;

    float acc[4][4][4];
    gemm_cp_main(g_o, g_wo, bm, bn, As, Bs, acc);

#pragma unroll
    for (int mt = 0; mt < 4; mt++)
#pragma unroll
        for (int nt = 0; nt < 4; nt++) {
            int m = bm + wm + mt * 16 + lr4;
            int n = bn + wn + (nt << 3) + (lc << 1);
            float2 r0v, r1v;
            r0v.x = acc[mt][nt][0] + bias[n];
            r0v.y = acc[mt][nt][1] + bias[n + 1];
            r1v.x = acc[mt][nt][2] + bias[n];
            r1v.y = acc[mt][nt][3] + bias[n + 1];
            *(float2*)&C[(size_t)m * DD + n]       = r0v;
            *(float2*)&C[(size_t)(m + 8) * DD + n] = r1v;
        }
}

// ---------------------------------------------------------------------------
// elementwise tf32 rounding
// ---------------------------------------------------------------------------
__global__ void cvt_tf32_kernel(const float* __restrict__ src, float* __restrict__ dst, int n) {
    int i = blockIdx.x * blockDim.x + threadIdx.x;
    if (i < n) dst[i] = __uint_as_float(f2tf32(src[i]));
}

// ---------------------------------------------------------------------------
// Gate: softmax over L of sqrt(Gr^2+Gi^2+eps)/temp, * gate_scale
// ---------------------------------------------------------------------------
__global__ __launch_bounds__(256) void gate_kernel(
    const float* __restrict__ G, const float* __restrict__ gs_p,
    const float* __restrict__ lt_p)
{
    __shared__ float sm[256];
    const int b = blockIdx.x, tid = threadIdx.x;
    const float inv_temp = __expf(-lt_p[0]);

    float z[8];
    float mx = -INFINITY;
#pragma unroll
    for (int i = 0; i < 8; i++) {
        int l = i * 256 + tid;
        float gr = G[(b * LL + l) * 2 + 0];
        float gi = G[(b * LL + l) * 2 + 1];
        z[i] = sqrtf(gr * gr + gi * gi + 1e-7f) * inv_temp;
        mx = fmaxf(mx, z[i]);
    }
    sm[tid] = mx; __syncthreads();
    for (int s = 128; s > 0; s >>= 1) {
        if (tid < s) sm[tid] = fmaxf(sm[tid], sm[tid + s]);
        __syncthreads();
    }
    const float gmax = sm[0];
    __syncthreads();

    float e[8]; float lsum = 0.f;
#pragma unroll
    for (int i = 0; i < 8; i++) { e[i] = __expf(z[i] - gmax); lsum += e[i]; }
    sm[tid] = lsum; __syncthreads();
    for (int s = 128; s > 0; s >>= 1) {
        if (tid < s) sm[tid] += sm[tid + s];
        __syncthreads();
    }
    const float inv_sum = 1.f / sm[0];
    const float gs = gs_p[0];
#pragma unroll
    for (int i = 0; i < 8; i++)
        g_gate[b * LL + i * 256 + tid] = e[i] * inv_sum * gs;
}

// ---------------------------------------------------------------------------
// Flash attention: R9/R10-proven cp.async pipeline + ldmatrix fragments.
// K [2][32][68] double-buffered ([key][d]); V now [64 d][36] (from g_vt
// [b,h,d,l] layout -> cp.async direct, k-contiguous rows => ldmatrix-able);
// P staged [128][36]. Per iter: S-B 16 LDSM (was 64 LDS), P-A 4 LDSM (was
// 16), V-B 16 LDSM (was 64). Values & accumulation order identical to R10.
// ---------------------------------------------------------------------------
__global__ __launch_bounds__(256, 2) void attn_cp() {
    __shared__ float Ks[2][32 * 68];
    __shared__ float Vs[64 * 36];
    __shared__ float Ps[128 * 36];

    const int tid = threadIdx.x, lane = tid & 31, wid = tid >> 5;
    const int bh = blockIdx.y, qbase = blockIdx.x << 7;
    const int lr4 = lane >> 2, lc = lane & 3;
    const int rq = wid * 16 + lr4;

    const float* Qg = g_q + ((size_t)bh * LL + qbase) * HD;
    const float* Kg = g_k + (size_t)bh * LL * HD;
    const float* Vg = g_vt + (size_t)bh * HD * LL;   // [d][l]

    // cp.async loader: K tile [32 key][64 d]
    const int krow = tid >> 3;            // 0..31
    const int kcol = (tid & 7) << 2;      // 0..28
    const uint32_t dK0 = smem_u32(&Ks[0][0]) + (krow * 68 + kcol) * 4;
    const uint32_t dK1 = smem_u32(&Ks[1][0]) + (krow * 68 + kcol) * 4;
    const float* Ksrc = Kg + krow * 64 + kcol;
    // V tile [64 d][32 key]: thread covers row d=tid>>2, chunks (tid&3)*4 and +16
    const int vd = tid >> 2, vc = (tid & 3) << 2;
    const uint32_t dV0 = smem_u32(Vs) + (vd * 36 + vc) * 4;
    const uint32_t dV1 = dV0 + 64;
    const float* Vsrc = Vg + (size_t)vd * LL + vc;

    // ldmatrix addresses
    const int r8 = lane & 7, j = lane >> 3;
    const int jm = (j & 1) << 3, jk = (j >> 1) << 2;   // A-pattern blocks
    const int jn = (j >> 1) << 3, jk2 = (j & 1) << 2;  // B-pattern blocks
    uint32_t kAddr[2], vAddr[4], pAddr;
#pragma unroll
    for (int p = 0; p < 2; p++)
        kAddr[p] = smem_u32(&Ks[0][0]) + 4u * ((p * 16 + jn + r8) * 68 + jk2);
#pragma unroll
    for (int p = 0; p < 4; p++)
        vAddr[p] = smem_u32(Vs) + 4u * ((p * 16 + jn + r8) * 36 + jk2);
    pAddr = smem_u32(Ps) + 4u * ((wid * 16 + jm + r8) * 36 + jk);

    // Q fragments (already *0.125 and tf32-rounded by QKV epilogue)
    unsigned qf[8][4];
#pragma unroll
    for (int k = 0; k < 8; k++) {
        int c = k * 8 + lc;
        qf[k][0] = __float_as_uint(Qg[rq * 64 + c]);
        qf[k][1] = __float_as_uint(Qg[(rq + 8) * 64 + c]);
        qf[k][2] = __float_as_uint(Qg[rq * 64 + c + 4]);
        qf[k][3] = __float_as_uint(Qg[(rq + 8) * 64 + c + 4]);
    }

    float oacc[8][4];
#pragma unroll
    for (int nt = 0; nt < 8; nt++)
#pragma unroll
        for (int i = 0; i < 4; i++) oacc[nt][i] = 0.f;
    float m_i[2] = {-INFINITY, -INFINITY};
    float l_i[2] = {0.f, 0.f};

    // prologue: K tile 0 -> Ks[0]
    cp_async16(dK0, Ksrc); cp_async16(dK0 + 128, Ksrc + 32);
    CP_COMMIT();

    for (int kt = 0; kt < LL / 32; kt++) {
        const int buf = kt & 1;
        const int kb = kt << 5;

        CP_WAIT(0);            // K(kt) complete (sole pending group)
        __syncthreads();

        // issue V(kt) (commit FIRST), then K(kt+1)
        cp_async16(dV0, Vsrc + kb); cp_async16(dV1, Vsrc + kb + 16);
        CP_COMMIT();
        if (kt < 63) {
            const float* ks2 = Ksrc + (kb + 32) * 64;
            const uint32_t dk = buf ? dK0 : dK1;
            cp_async16(dk, ks2); cp_async16(dk + 128, ks2 + 32);
            CP_COMMIT();
        }

        // S-GEMM on Ks[buf] via ldmatrix
        float sacc[4][4];
#pragma unroll
        for (int nt = 0; nt < 4; nt++)
#pragma unroll
            for (int i = 0; i < 4; i++) sacc[nt][i] = 0.f;
        const uint32_t koff = (uint32_t)buf * (32 * 68 * 4);
#pragma unroll
        for (int k = 0; k < 8; k++) {
            unsigned bb[2][4];
            LDSM4(bb[0][0], bb[0][1], bb[0][2], bb[0][3], kAddr[0] + koff + k * 32);
            LDSM4(bb[1][0], bb[1][1], bb[1][2], bb[1][3], kAddr[1] + koff + k * 32);
#pragma unroll
            for (int nt = 0; nt < 4; nt++)
                mma_tf32(sacc[nt], qf[k], &bb[nt >> 1][(nt & 1) << 1]);
        }

        // online softmax; stage tf32 P into per-warp smem rows
#pragma unroll
        for (int h2 = 0; h2 < 2; h2++) {
            float rm = -INFINITY;
#pragma unroll
            for (int nt = 0; nt < 4; nt++)
                rm = fmaxf(rm, fmaxf(sacc[nt][h2 * 2], sacc[nt][h2 * 2 + 1]));
            rm = fmaxf(rm, __shfl_xor_sync(0xffffffffu, rm, 1));
            rm = fmaxf(rm, __shfl_xor_sync(0xffffffffu, rm, 2));
            float mn = fmaxf(m_i[h2], rm);
            float corr = __expf(m_i[h2] - mn);
            m_i[h2] = mn;
            float rs = 0.f;
#pragma unroll
            for (int nt = 0; nt < 4; nt++) {
                float p0 = __expf(sacc[nt][h2 * 2] - mn);
                float p1 = __expf(sacc[nt][h2 * 2 + 1] - mn);
                rs += p0 + p1;
                float2 pv;
                pv.x = __uint_as_float(f2tf32(p0));
                pv.y = __uint_as_float(f2tf32(p1));
                *(float2*)&Ps[(rq + h2 * 8) * 36 + nt * 8 + lc * 2] = pv;
            }
            rs += __shfl_xor_sync(0xffffffffu, rs, 1);
            rs += __shfl_xor_sync(0xffffffffu, rs, 2);
            l_i[h2] = l_i[h2] * corr + rs;
#pragma unroll
            for (int nt = 0; nt < 8; nt++) {
                oacc[nt][h2 * 2]     *= corr;
                oacc[nt][h2 * 2 + 1] *= corr;
            }
        }

        if (kt < 63) { CP_WAIT(1); }   // V(kt) done; K(kt+1) may remain
        else         { CP_WAIT(0); }
        __syncthreads();               // Vs visible; Ps visible

        // O += P V via ldmatrix (Vs is [d][36], k-contiguous rows)
#pragma unroll
        for (int kc = 0; kc < 4; kc++) {
            unsigned a[4];
            LDSM4(a[0], a[1], a[2], a[3], pAddr + kc * 32);
            unsigned vb[4][4];
#pragma unroll
            for (int p = 0; p < 4; p++)
                LDSM4(vb[p][0], vb[p][1], vb[p][2], vb[p][3], vAddr[p] + kc * 32);
#pragma unroll
            for (int nt = 0; nt < 8; nt++)
                mma_tf32(oacc[nt], a, &vb[nt >> 1][(nt & 1) << 1]);
        }
    }

    // Epilogue: 1/l, gate, tf32 round, scatter to (b, l, h*64+d)
    const int b = bh >> 4, h = bh & 15;
#pragma unroll
    for (int h2 = 0; h2 < 2; h2++) {
        int q = qbase + rq + h2 * 8;
        float sc = g_gate[b * LL + q] / l_i[h2];
        float* dst = g_o + ((size_t)(b * LL + q)) * DD + h * HD;
#pragma unroll
        for (int nt = 0; nt < 8; nt++) {
            int d = nt * 8 + lc * 2;
            float2 ov;
            ov.x = __uint_as_float(f2tf32(oacc[nt][h2 * 2] * sc));
            ov.y = __uint_as_float(f2tf32(oacc[nt][h2 * 2 + 1] * sc));
            *(float2*)(dst + d) = ov;
        }
    }
}

// ---------------------------------------------------------------------------
extern "C" void kernel_launch(void* const* d_in, const int* in_sizes, int n_in,
                              void* d_out, int out_size)
{
    const float* x    = (const float*)d_in[0];
    const float* G    = (const float*)d_in[1];
    const float* qkvw = (const float*)d_in[2];
    const float* outw = (const float*)d_in[3];
    const float* outb = (const float*)d_in[4];
    const float* gsc  = (const float*)d_in[5];
    const float* ltm  = (const float*)d_in[6];
    float* out = (float*)d_out;

    float* xt; cudaGetSymbolAddress((void**)&xt, g_xt);
    float* wq; cudaGetSymbolAddress((void**)&wq, g_wq);
    float* wo; cudaGetSymbolAddress((void**)&wo, g_wo);

    cvt_tf32_kernel<<<(MM * DD) / 256, 256>>>(x, xt, MM * DD);
    cvt_tf32_kernel<<<(N_QKV * DD) / 256, 256>>>(qkvw, wq, N_QKV * DD);
    cvt_tf32_kernel<<<(DD * DD) / 256, 256>>>(outw, wo, DD * DD);

    dim3 g1(N_QKV / 128, MM / 128);   // (24, 32)
    qkv_gemm_cp<<<g1, 256>>>();

    gate_kernel<<<BB, 256>>>(G, gsc, ltm);

    dim3 g2(LL / 128, BB * HH);       // (16, 32)
    attn_cp<<<g2, 256>>>();

    dim3 g3(DD / 128, MM / 128);      // (8, 32)
    out_gemm_cp<<<g3, 256>>>(outb, out);
}